// round 14
// baseline (speedup 1.0000x reference)
#include <cuda_runtime.h>
#include <cuda_fp16.h>
#include <cstdint>
#include <cstddef>

#define B_   2
#define L_   2048
#define D_   1024
#define H_   16
#define HD_  64
#define BL_  (B_ * L_)
#define NBIAS_ 257
#define STR  40   // smem row stride (halfs) for 32-wide half tiles
#define STR2 72   // smem row stride (halfs) for 64-wide half tiles

static const size_t OUT_ELEMS = (size_t)BL_ * D_;
static const size_t ATT_ELEMS = (size_t)B_ * H_ * L_ * (size_t)L_;

// Device-global scratch (allocation-free rule)
__device__ float  g_V[(size_t)BL_ * D_];
__device__ __half g_Xh[3ull * BL_ * D_], g_Xl[3ull * BL_ * D_];
__device__ __half g_Qh[(size_t)BL_ * D_], g_Ql[(size_t)BL_ * D_];
__device__ __half g_Kh[(size_t)BL_ * D_], g_Kl[(size_t)BL_ * D_];
__device__ __half g_Ch[(size_t)BL_ * D_], g_Cl[(size_t)BL_ * D_];
__device__ __half g_Wth[4ull * D_ * D_];
__device__ __half g_Wtl[4ull * D_ * D_];
__device__ __half g_Vth[(size_t)BL_ * D_]; // V transposed: [(b*16+h)*64+d][tok]
__device__ __half g_Vtl[(size_t)BL_ * D_];
__device__ float2 g_pstats[(size_t)B_ * H_ * L_ * 16];
__device__ float  g_attn[(size_t)B_ * H_ * L_ * (size_t)L_]; // fallback

// ---------------------------------------------------------------------------
// Helpers
// ---------------------------------------------------------------------------
__device__ __forceinline__ uint32_t smem_u32(const void* p) {
    uint32_t a;
    asm("{ .reg .u64 t; cvta.to.shared.u64 t, %1; cvt.u32.u64 %0, t; }" : "=r"(a) : "l"(p));
    return a;
}
__device__ __forceinline__ void cpa16(uint32_t d, const void* s) {
    asm volatile("cp.async.cg.shared.global [%0], [%1], 16;" :: "r"(d), "l"(s));
}
#define CP_COMMIT() asm volatile("cp.async.commit_group;" ::: "memory")
#define CP_WAIT0()  asm volatile("cp.async.wait_group 0;" ::: "memory")
#define CP_WAIT1()  asm volatile("cp.async.wait_group 1;" ::: "memory")

__device__ __forceinline__ void ldsm4(uint32_t r[4], uint32_t addr) {
    asm volatile("ldmatrix.sync.aligned.m8n8.x4.shared.b16 {%0,%1,%2,%3}, [%4];"
                 : "=r"(r[0]), "=r"(r[1]), "=r"(r[2]), "=r"(r[3]) : "r"(addr));
}
__device__ __forceinline__ void ldsm2(uint32_t r[2], uint32_t addr) {
    asm volatile("ldmatrix.sync.aligned.m8n8.x2.shared.b16 {%0,%1}, [%2];"
                 : "=r"(r[0]), "=r"(r[1]) : "r"(addr));
}
__device__ __forceinline__ void mma16816(float c[4], const uint32_t a[4], const uint32_t b[2]) {
    asm volatile("mma.sync.aligned.m16n8k16.row.col.f32.f16.f16.f32 "
                 "{%0,%1,%2,%3}, {%4,%5,%6,%7}, {%8,%9}, {%0,%1,%2,%3};"
                 : "+f"(c[0]), "+f"(c[1]), "+f"(c[2]), "+f"(c[3])
                 : "r"(a[0]), "r"(a[1]), "r"(a[2]), "r"(a[3]), "r"(b[0]), "r"(b[1]));
}

__device__ __forceinline__ uint32_t h2u(__half2 v) { return *reinterpret_cast<uint32_t*>(&v); }

__device__ __forceinline__ void split2(float x, float y, uint32_t& hi, uint32_t& lo) {
    __half h0 = __float2half_rn(x), h1 = __float2half_rn(y);
    __half l0 = __float2half_rn(x - __half2float(h0));
    __half l1 = __float2half_rn(y - __half2float(h1));
    hi = h2u(__halves2half2(h0, h1));
    lo = h2u(__halves2half2(l0, l1));
}

// Async copy of half tile [rows][32] (gs = global row stride, halfs)
__device__ __forceinline__ void cp_half32(const __half* __restrict__ g, int gs,
                                          uint32_t sm, int tid, int rows) {
    int c = tid & 3, r0 = tid >> 2;
    for (int r = r0; r < rows; r += 64)
        cpa16(sm + (uint32_t)(r * STR + c * 8) * 2, g + (size_t)r * gs + c * 8);
}
// Async copy of half tile [rows][64], stride STR2
__device__ __forceinline__ void cp_half64(const __half* __restrict__ g, int gs,
                                          uint32_t sm, int tid, int rows) {
    int c = tid & 7, r0 = tid >> 3;
    for (int r = r0; r < rows; r += 32)
        cpa16(sm + (uint32_t)(r * STR2 + c * 8) * 2, g + (size_t)r * gs + c * 8);
}

// ---------------------------------------------------------------------------
// Prep kernels
// ---------------------------------------------------------------------------
__global__ __launch_bounds__(256) void xsplit(
    const float* __restrict__ X0, const float* __restrict__ X1,
    const float* __restrict__ X2, __half* __restrict__ Xh, __half* __restrict__ Xl)
{
    const float* Xs[3] = {X0, X1, X2};
    const float* X = Xs[blockIdx.y];
    __half* xh = Xh + (size_t)blockIdx.y * BL_ * D_;
    __half* xl = Xl + (size_t)blockIdx.y * BL_ * D_;
    size_t i = ((size_t)blockIdx.x * 256 + threadIdx.x) * 8;
    float4 a = *(const float4*)(X + i);
    float4 b = *(const float4*)(X + i + 4);
    uint32_t h0, l0, h1, l1, h2, l2, h3, l3;
    split2(a.x, a.y, h0, l0);
    split2(a.z, a.w, h1, l1);
    split2(b.x, b.y, h2, l2);
    split2(b.z, b.w, h3, l3);
    *(uint4*)(xh + i) = make_uint4(h0, h1, h2, h3);
    *(uint4*)(xl + i) = make_uint4(l0, l1, l2, l3);
}

__global__ void wsplit4(const float* __restrict__ W0, const float* __restrict__ W1,
                        const float* __restrict__ W2, const float* __restrict__ W3,
                        __half* __restrict__ Th, __half* __restrict__ Tl) {
    __shared__ float t[32][33];
    const float* Ws[4] = {W0, W1, W2, W3};
    const float* W = Ws[blockIdx.z];
    __half* th = Th + (size_t)blockIdx.z * D_ * D_;
    __half* tl = Tl + (size_t)blockIdx.z * D_ * D_;
    int bx = blockIdx.x * 32, by = blockIdx.y * 32;
    int tx = threadIdx.x, ty = threadIdx.y;
    for (int i = ty; i < 32; i += 8)
        t[i][tx] = W[(size_t)(by + i) * D_ + bx + tx];
    __syncthreads();
    for (int i = ty; i < 32; i += 8) {
        float v = t[tx][i];
        __half h = __float2half_rn(v);
        th[(size_t)(bx + i) * D_ + by + tx] = h;
        tl[(size_t)(bx + i) * D_ + by + tx] = __float2half_rn(v - __half2float(h));
    }
}
__global__ void vsplit(const float* __restrict__ V, __half* __restrict__ Th,
                       __half* __restrict__ Tl) {
    __shared__ float t[32][33];
    int bx = blockIdx.x * 32, by = blockIdx.y * 32;
    int tx = threadIdx.x, ty = threadIdx.y;
    for (int i = ty; i < 32; i += 8)
        t[i][tx] = V[(size_t)(by + i) * D_ + bx + tx];
    __syncthreads();
    int tok = by + tx;
    int b = tok >> 11, tokin = tok & (L_ - 1);
    for (int i = ty; i < 32; i += 8) {
        int f = bx + i;
        float v = t[tx][i];
        size_t row = ((size_t)(b * H_ + (f >> 6))) * 64 + (f & 63);
        __half h = __float2half_rn(v);
        Th[row * L_ + tokin] = h;
        Tl[row * L_ + tokin] = __float2half_rn(v - __half2float(h));
    }
}

// ---------------------------------------------------------------------------
// Shared MMA block helper (term-major issue order), A/B stride STR
// ---------------------------------------------------------------------------
#define PJ_PL   (128 * STR)
#define PJ_BUF  (4 * PJ_PL)
#define PJ_SMEM (2 * PJ_BUF * 2)

template <int NI>
__device__ __forceinline__ void mma_block(
    float acc[4][NI][4], const uint32_t pAh, const uint32_t pAl,
    const uint32_t pBh, const uint32_t pBl,
    int wm, int wn, int lane)
{
#pragma unroll
    for (int ks = 0; ks < 32; ks += 16) {
        uint32_t ah[4][4], al[4][4], bh[NI][2], bl[NI][2];
        const uint32_t aoff = (uint32_t)((wm * 64 + (lane & 15)) * STR + ks + (lane >> 4) * 8) * 2;
        const uint32_t boff = (uint32_t)((wn * (8 * NI) + (lane & 7)) * STR + ks + ((lane >> 3) & 1) * 8) * 2;
#pragma unroll
        for (int mi = 0; mi < 4; mi++) {
            ldsm4(ah[mi], pAh + aoff + mi * 16 * STR * 2);
            ldsm4(al[mi], pAl + aoff + mi * 16 * STR * 2);
        }
#pragma unroll
        for (int ni = 0; ni < NI; ni++) {
            ldsm2(bh[ni], pBh + boff + ni * 8 * STR * 2);
            ldsm2(bl[ni], pBl + boff + ni * 8 * STR * 2);
        }
#pragma unroll
        for (int mi = 0; mi < 4; mi++)
#pragma unroll
            for (int ni = 0; ni < NI; ni++) mma16816(acc[mi][ni], ah[mi], bh[ni]);
#pragma unroll
        for (int mi = 0; mi < 4; mi++)
#pragma unroll
            for (int ni = 0; ni < NI; ni++) mma16816(acc[mi][ni], ah[mi], bl[ni]);
#pragma unroll
        for (int mi = 0; mi < 4; mi++)
#pragma unroll
            for (int ni = 0; ni < NI; ni++) mma16816(acc[mi][ni], al[mi], bh[ni]);
    }
}

// ---------------------------------------------------------------------------
// Merged Q/K/V projection: grid (8, 32, 3)
// ---------------------------------------------------------------------------
__global__ __launch_bounds__(256, 2) void qkv_proj(
    const __half* __restrict__ Xh, const __half* __restrict__ Xl,
    const __half* __restrict__ Wth, const __half* __restrict__ Wtl,
    const float* __restrict__ bq, const float* __restrict__ bk,
    const float* __restrict__ bv,
    __half* __restrict__ Qh, __half* __restrict__ Ql,
    __half* __restrict__ Kh, __half* __restrict__ Kl,
    float* __restrict__ Vp)
{
    extern __shared__ __half dsm[];
    const int tid = threadIdx.x, wid = tid >> 5, lane = tid & 31;
    const int wm = wid >> 2, wn = wid & 3;
    const int n0 = blockIdx.x * 128, m0 = blockIdx.y * 128;
    const int z = blockIdx.z;
    const uint32_t sb = smem_u32(dsm);

    const __half* Ahg = Xh + (size_t)z * BL_ * D_;
    const __half* Alg = Xl + (size_t)z * BL_ * D_;
    const __half* Bth = Wth + (size_t)z * D_ * D_;
    const __half* Btl = Wtl + (size_t)z * D_ * D_;
    const float* bias = (z == 0) ? bq : (z == 1) ? bk : bv;

    float acc[4][4][4];
#pragma unroll
    for (int i = 0; i < 4; i++)
#pragma unroll
        for (int j = 0; j < 4; j++)
#pragma unroll
            for (int f = 0; f < 4; f++) acc[i][j][f] = 0.0f;

    const int NT = D_ / 32;

    auto stage = [&](int kt, int buf) {
        const int k0 = kt * 32;
        uint32_t ub = sb + (uint32_t)(buf * PJ_BUF) * 2;
        cp_half32(Ahg + (size_t)m0 * D_ + k0, D_, ub + 0 * PJ_PL * 2, tid, 128);
        cp_half32(Alg + (size_t)m0 * D_ + k0, D_, ub + 1 * PJ_PL * 2, tid, 128);
        cp_half32(Bth + (size_t)n0 * D_ + k0, D_, ub + 2 * PJ_PL * 2, tid, 128);
        cp_half32(Btl + (size_t)n0 * D_ + k0, D_, ub + 3 * PJ_PL * 2, tid, 128);
        CP_COMMIT();
    };

    stage(0, 0);
    stage(1, 1);

    for (int kt = 0; kt < NT; kt++) {
        if (kt + 1 < NT) { CP_WAIT1(); } else { CP_WAIT0(); }
        __syncthreads();
        const int buf = kt & 1;
        mma_block<4>(acc,
                     sb + (uint32_t)(buf * PJ_BUF + 0 * PJ_PL) * 2,
                     sb + (uint32_t)(buf * PJ_BUF + 1 * PJ_PL) * 2,
                     sb + (uint32_t)(buf * PJ_BUF + 2 * PJ_PL) * 2,
                     sb + (uint32_t)(buf * PJ_BUF + 3 * PJ_PL) * 2,
                     wm, wn, lane);
        __syncthreads();
        if (kt + 2 < NT) stage(kt + 2, buf);
    }

#pragma unroll
    for (int mi = 0; mi < 4; mi++)
#pragma unroll
        for (int ni = 0; ni < 4; ni++) {
            int r = m0 + wm * 64 + mi * 16 + (lane >> 2);
            int cc = n0 + wn * 32 + ni * 8 + (lane & 3) * 2;
            float b0 = bias[cc], b1 = bias[cc + 1];
            float v0 = acc[mi][ni][0] + b0, v1 = acc[mi][ni][1] + b1;
            float v2 = acc[mi][ni][2] + b0, v3 = acc[mi][ni][3] + b1;
            if (z == 2) {
                *(float2*)(Vp + (size_t)r * D_ + cc) = make_float2(v0, v1);
                *(float2*)(Vp + (size_t)(r + 8) * D_ + cc) = make_float2(v2, v3);
            } else {
                __half* Ch = (z == 0) ? Qh : Kh;
                __half* Cl = (z == 0) ? Ql : Kl;
                uint32_t h, l;
                split2(v0, v1, h, l);
                *(uint32_t*)(Ch + (size_t)r * D_ + cc) = h;
                *(uint32_t*)(Cl + (size_t)r * D_ + cc) = l;
                split2(v2, v3, h, l);
                *(uint32_t*)(Ch + (size_t)(r + 8) * D_ + cc) = h;
                *(uint32_t*)(Cl + (size_t)(r + 8) * D_ + cc) = l;
            }
        }
}

// ---------------------------------------------------------------------------
// Output projection
// ---------------------------------------------------------------------------
__global__ __launch_bounds__(256, 2) void out_proj(
    const __half* __restrict__ Ahg, const __half* __restrict__ Alg,
    const __half* __restrict__ Bth, const __half* __restrict__ Btl,
    const float* __restrict__ bias, float* __restrict__ C32)
{
    extern __shared__ __half dsm[];
    const int tid = threadIdx.x, wid = tid >> 5, lane = tid & 31;
    const int wm = wid >> 2, wn = wid & 3;
    const int n0 = blockIdx.x * 128, m0 = blockIdx.y * 128;
    const uint32_t sb = smem_u32(dsm);

    float acc[4][4][4];
#pragma unroll
    for (int i = 0; i < 4; i++)
#pragma unroll
        for (int j = 0; j < 4; j++)
#pragma unroll
            for (int f = 0; f < 4; f++) acc[i][j][f] = 0.0f;

    const int NT = D_ / 32;

    auto stage = [&](int kt, int buf) {
        const int k0 = kt * 32;
        uint32_t ub = sb + (uint32_t)(buf * PJ_BUF) * 2;
        cp_half32(Ahg + (size_t)m0 * D_ + k0, D_, ub + 0 * PJ_PL * 2, tid, 128);
        cp_half32(Alg + (size_t)m0 * D_ + k0, D_, ub + 1 * PJ_PL * 2, tid, 128);
        cp_half32(Bth + (size_t)n0 * D_ + k0, D_, ub + 2 * PJ_PL * 2, tid, 128);
        cp_half32(Btl + (size_t)n0 * D_ + k0, D_, ub + 3 * PJ_PL * 2, tid, 128);
        CP_COMMIT();
    };

    stage(0, 0);
    stage(1, 1);

    for (int kt = 0; kt < NT; kt++) {
        if (kt + 1 < NT) { CP_WAIT1(); } else { CP_WAIT0(); }
        __syncthreads();
        const int buf = kt & 1;
        mma_block<4>(acc,
                     sb + (uint32_t)(buf * PJ_BUF + 0 * PJ_PL) * 2,
                     sb + (uint32_t)(buf * PJ_BUF + 1 * PJ_PL) * 2,
                     sb + (uint32_t)(buf * PJ_BUF + 2 * PJ_PL) * 2,
                     sb + (uint32_t)(buf * PJ_BUF + 3 * PJ_PL) * 2,
                     wm, wn, lane);
        __syncthreads();
        if (kt + 2 < NT) stage(kt + 2, buf);
    }

#pragma unroll
    for (int mi = 0; mi < 4; mi++)
#pragma unroll
        for (int ni = 0; ni < 4; ni++) {
            int r = m0 + wm * 64 + mi * 16 + (lane >> 2);
            int cc = n0 + wn * 32 + ni * 8 + (lane & 3) * 2;
            float b0 = bias[cc], b1 = bias[cc + 1];
            *(float2*)(C32 + (size_t)r * D_ + cc) =
                make_float2(acc[mi][ni][0] + b0, acc[mi][ni][1] + b1);
            *(float2*)(C32 + (size_t)(r + 8) * D_ + cc) =
                make_float2(acc[mi][ni][2] + b0, acc[mi][ni][3] + b1);
        }
}

// ---------------------------------------------------------------------------
// Scores stats pass: identical MMA + bias, but NO raw-S stores.
// Emits only per-(row, ktile) partial (max, sum).
// ---------------------------------------------------------------------------
#define SC_PL   (128 * STR2)
#define SC_SMEM (4 * SC_PL * 2)

__global__ __launch_bounds__(256, 2) void scores_stats(
    const float* __restrict__ rel_bias, float2* __restrict__ pstats)
{
    extern __shared__ __half dsm[];
    __shared__ float sbias[NBIAS_];

    const int tid = threadIdx.x, wid = tid >> 5, lane = tid & 31;
    const int wm = wid >> 2, wn = wid & 3;
    const int bx = blockIdx.x, by = blockIdx.y, bh_ = blockIdx.z;
    const int b = bh_ >> 4, h = bh_ & 15;
    const uint32_t sb = smem_u32(dsm);

    const size_t qb = (size_t)(b * L_ + by * 128) * D_ + h * HD_;
    const size_t kb = (size_t)(b * L_ + bx * 128) * D_ + h * HD_;

    cp_half64(g_Qh + qb, D_, sb + 0u * SC_PL * 2, tid, 128);
    cp_half64(g_Ql + qb, D_, sb + 1u * SC_PL * 2, tid, 128);
    cp_half64(g_Kh + kb, D_, sb + 2u * SC_PL * 2, tid, 128);
    cp_half64(g_Kl + kb, D_, sb + 3u * SC_PL * 2, tid, 128);
    CP_COMMIT();

    for (int i = tid; i < NBIAS_; i += 256) sbias[i] = rel_bias[i * H_ + h];

    float acc[4][4][4];
#pragma unroll
    for (int i = 0; i < 4; i++)
#pragma unroll
        for (int j = 0; j < 4; j++)
#pragma unroll
            for (int f = 0; f < 4; f++) acc[i][j][f] = 0.0f;

    CP_WAIT0();
    __syncthreads();

    const uint32_t pAh = sb + 0u * SC_PL * 2, pAl = sb + 1u * SC_PL * 2;
    const uint32_t pBh = sb + 2u * SC_PL * 2, pBl = sb + 3u * SC_PL * 2;
#pragma unroll
    for (int ks = 0; ks < 64; ks += 16) {
        uint32_t ah[4][4], al[4][4], bh[4][2], bl[4][2];
        const uint32_t aoff = (uint32_t)((wm * 64 + (lane & 15)) * STR2 + ks + (lane >> 4) * 8) * 2;
        const uint32_t boff = (uint32_t)((wn * 32 + (lane & 7)) * STR2 + ks + ((lane >> 3) & 1) * 8) * 2;
#pragma unroll
        for (int mi = 0; mi < 4; mi++) {
            ldsm4(ah[mi], pAh + aoff + mi * 16 * STR2 * 2);
            ldsm4(al[mi], pAl + aoff + mi * 16 * STR2 * 2);
        }
#pragma unroll
        for (int ni = 0; ni < 4; ni++) {
            ldsm2(bh[ni], pBh + boff + ni * 8 * STR2 * 2);
            ldsm2(bl[ni], pBl + boff + ni * 8 * STR2 * 2);
        }
#pragma unroll
        for (int mi = 0; mi < 4; mi++)
#pragma unroll
            for (int ni = 0; ni < 4; ni++) mma16816(acc[mi][ni], ah[mi], bh[ni]);
#pragma unroll
        for (int mi = 0; mi < 4; mi++)
#pragma unroll
            for (int ni = 0; ni < 4; ni++) mma16816(acc[mi][ni], ah[mi], bl[ni]);
#pragma unroll
        for (int mi = 0; mi < 4; mi++)
#pragma unroll
            for (int ni = 0; ni < 4; ni++) mma16816(acc[mi][ni], al[mi], bh[ni]);
    }

    __syncthreads();
    float* red_m = (float*)dsm;          // [128][4]
    float* red_s = (float*)dsm + 512;    // [128][4]

#pragma unroll
    for (int mi = 0; mi < 4; mi++)
#pragma unroll
        for (int rh = 0; rh < 2; rh++) {
            int rl = wm * 64 + mi * 16 + rh * 8 + (lane >> 2);
            int q = by * 128 + rl;
            float v[8];
#pragma unroll
            for (int ni = 0; ni < 4; ni++) {
                int kc = bx * 128 + wn * 32 + ni * 8 + (lane & 3) * 2;
                int rel0 = kc - q;     rel0 = rel0 < -128 ? -128 : (rel0 > 128 ? 128 : rel0);
                int rel1 = kc + 1 - q; rel1 = rel1 < -128 ? -128 : (rel1 > 128 ? 128 : rel1);
                v[ni * 2 + 0] = acc[mi][ni][rh * 2 + 0] * 0.125f + sbias[rel0 + 128];
                v[ni * 2 + 1] = acc[mi][ni][rh * 2 + 1] * 0.125f + sbias[rel1 + 128];
            }
            float m = v[0];
#pragma unroll
            for (int i = 1; i < 8; i++) m = fmaxf(m, v[i]);
            m = fmaxf(m, __shfl_xor_sync(0xffffffffu, m, 1));
            m = fmaxf(m, __shfl_xor_sync(0xffffffffu, m, 2));
            float s = 0.0f;
#pragma unroll
            for (int i = 0; i < 8; i++) s += __expf(v[i] - m);
            s += __shfl_xor_sync(0xffffffffu, s, 1);
            s += __shfl_xor_sync(0xffffffffu, s, 2);
            if ((lane & 3) == 0) {
                red_m[rl * 4 + wn] = m;
                red_s[rl * 4 + wn] = s;
            }
        }
    __syncthreads();
    if (tid < 128) {
        float m0 = red_m[tid * 4 + 0], m1 = red_m[tid * 4 + 1];
        float m2 = red_m[tid * 4 + 2], m3 = red_m[tid * 4 + 3];
        float M = fmaxf(fmaxf(m0, m1), fmaxf(m2, m3));
        float S = red_s[tid * 4 + 0] * __expf(m0 - M) + red_s[tid * 4 + 1] * __expf(m1 - M)
                + red_s[tid * 4 + 2] * __expf(m2 - M) + red_s[tid * 4 + 3] * __expf(m3 - M);
        pstats[((size_t)bh_ * L_ + by * 128 + tid) * 16 + bx] = make_float2(M, S);
    }
}

// ---------------------------------------------------------------------------
// Flash-style av: Q tile resident; per 32-token chunk recompute S (bit-
// identical accumulation order to scores_stats), exp with final stats,
// write normalized P fp32 (the attention output), and PV-MMA on P halves.
// smem (bytes):
//  [0]      Qh 128xSTR2 (18432), Ql (18432)
//  [36864]  K: 2 bufs x (Kh 32xSTR2 4608 + Kl 4608) = 18432
//  [55296]  V: 2 bufs x (Vh 64xSTR 5120 + Vl 5120) = 20480
//  [75776]  Ph 128xSTR (10240), Pl (10240)
//  [96256]  stats float2[128] (1024)
// ---------------------------------------------------------------------------
#define AF_QH 0
#define AF_QL 18432
#define AF_K  36864
#define AF_V  55296
#define AF_PH 75776
#define AF_PL 86016
#define AF_ST 96256
#define AF_SMEM 97280

__global__ __launch_bounds__(256, 2) void av_flash(
    const float* __restrict__ rel_bias, float* __restrict__ attn,
    const float2* __restrict__ pstats)
{
    extern __shared__ char dsmc[];
    __shared__ float sbias[NBIAS_];
    float2* sst = (float2*)(dsmc + AF_ST);

    const int tid = threadIdx.x, wid = tid >> 5, lane = tid & 31;
    const int wm = wid >> 2, wn = wid & 3;
    const int by = blockIdx.x, bh_ = blockIdx.y;
    const int b = bh_ >> 4, h = bh_ & 15;
    const uint32_t sb = smem_u32(dsmc);

    const size_t qb = (size_t)(b * L_ + by * 128) * D_ + h * HD_;
    const size_t kgb = (size_t)(b * L_) * D_ + h * HD_;
    const size_t vbase = (size_t)bh_ * 64 * L_;
    const size_t pb = ((size_t)bh_ * L_ + by * 128) * L_;

    for (int i = tid; i < NBIAS_; i += 256) sbias[i] = rel_bias[i * H_ + h];

    auto stage = [&](int kt, int buf) {
        const int k0 = kt * 32;
        uint32_t kb = sb + AF_K + (uint32_t)buf * 9216;
        cp_half64(g_Kh + kgb + (size_t)k0 * D_, D_, kb, tid, 32);
        cp_half64(g_Kl + kgb + (size_t)k0 * D_, D_, kb + 4608, tid, 32);
        uint32_t vb = sb + AF_V + (uint32_t)buf * 10240;
        cp_half32(g_Vth + vbase + k0, L_, vb, tid, 64);
        cp_half32(g_Vtl + vbase + k0, L_, vb + 5120, tid, 64);
        CP_COMMIT();
    };

    // Q tile resident (committed with stage 0)
    cp_half64(g_Qh + qb, D_, sb + AF_QH, tid, 128);
    cp_half64(g_Ql + qb, D_, sb + AF_QL, tid, 128);
    stage(0, 0);
    stage(1, 1);

    // combine partial stats for this CTA's 128 rows
    if (tid < 128) {
        const float2* p = pstats + ((size_t)bh_ * L_ + by * 128 + tid) * 16;
        float2 v[16];
#pragma unroll
        for (int i = 0; i < 16; i++) v[i] = p[i];
        float M = v[0].x;
#pragma unroll
        for (int i = 1; i < 16; i++) M = fmaxf(M, v[i].x);
        float S = 0.0f;
#pragma unroll
        for (int i = 0; i < 16; i++) S += v[i].y * __expf(v[i].x - M);
        sst[tid] = make_float2(M, 1.0f / S);
    }

    float cacc[4][2][4];
#pragma unroll
    for (int i = 0; i < 4; i++)
#pragma unroll
        for (int j = 0; j < 2; j++)
#pragma unroll
            for (int f = 0; f < 4; f++) cacc[i][j][f] = 0.0f;

    const int NT = L_ / 32;

    for (int kt = 0; kt < NT; kt++) {
        if (kt + 1 < NT) { CP_WAIT1(); } else { CP_WAIT0(); }
        __syncthreads();
        const int buf = kt & 1;
        const int k0 = kt * 32;

        // --- S recompute: 128q x 32tok, Kdim = 64 ---
        float sacc[4][4];
#pragma unroll
        for (int mi = 0; mi < 4; mi++)
#pragma unroll
            for (int f = 0; f < 4; f++) sacc[mi][f] = 0.0f;

        const uint32_t kbh = sb + AF_K + (uint32_t)buf * 9216;
        const uint32_t kbl = kbh + 4608;
#pragma unroll
        for (int ks = 0; ks < 64; ks += 16) {
            uint32_t ah[4][4], al[4][4], bh[2], bl[2];
            const uint32_t aoff = (uint32_t)((wm * 64 + (lane & 15)) * STR2 + ks + (lane >> 4) * 8) * 2;
            const uint32_t boff = (uint32_t)((wn * 8 + (lane & 7)) * STR2 + ks + ((lane >> 3) & 1) * 8) * 2;
#pragma unroll
            for (int mi = 0; mi < 4; mi++) {
                ldsm4(ah[mi], sb + AF_QH + aoff + mi * 16 * STR2 * 2);
                ldsm4(al[mi], sb + AF_QL + aoff + mi * 16 * STR2 * 2);
            }
            ldsm2(bh, kbh + boff);
            ldsm2(bl, kbl + boff);
#pragma unroll
            for (int mi = 0; mi < 4; mi++) mma16816(sacc[mi], ah[mi], bh);
#pragma unroll
            for (int mi = 0; mi < 4; mi++) mma16816(sacc[mi], ah[mi], bl);
#pragma unroll
            for (int mi = 0; mi < 4; mi++) mma16816(sacc[mi], al[mi], bh);
        }

        // --- exp epilogue: write normalized P fp32 + P halves to smem ---
#pragma unroll
        for (int mi = 0; mi < 4; mi++)
#pragma unroll
            for (int rh = 0; rh < 2; rh++) {
                int rl = wm * 64 + mi * 16 + rh * 8 + (lane >> 2);
                int q = by * 128 + rl;
                int col = wn * 8 + (lane & 3) * 2;   // 0..31 within chunk
                int kc = k0 + col;
                int rel0 = kc - q;     rel0 = rel0 < -128 ? -128 : (rel0 > 128 ? 128 : rel0);
                int rel1 = kc + 1 - q; rel1 = rel1 < -128 ? -128 : (rel1 > 128 ? 128 : rel1);
                float s0 = sacc[mi][rh * 2 + 0] * 0.125f + sbias[rel0 + 128];
                float s1 = sacc[mi][rh * 2 + 1] * 0.125f + sbias[rel1 + 128];
                float2 ms = sst[rl];
                float p0 = __expf(s0 - ms.x);
                float p1 = __expf(s1 - ms.x);
                *(float2*)(attn + pb + (size_t)rl * L_ + kc) =
                    make_float2(p0 * ms.y, p1 * ms.y);
                uint32_t hw, lw;
                split2(p0, p1, hw, lw);
                *(uint32_t*)(dsmc + AF_PH + (rl * STR + col) * 2) = hw;
                *(uint32_t*)(dsmc + AF_PL + (rl * STR + col) * 2) = lw;
            }
        __syncthreads();

        // --- PV MMA: P(128x32) x Vt(64x32)^T ---
        const uint32_t vbh = sb + AF_V + (uint32_t)buf * 10240;
        mma_block<2>(cacc, sb + AF_PH, sb + AF_PL, vbh, vbh + 5120, wm, wn, lane);
        __syncthreads();
        if (kt + 2 < NT) stage(kt + 2, buf);
    }

#pragma unroll
    for (int mi = 0; mi < 4; mi++)
#pragma unroll
        for (int ni = 0; ni < 2; ni++) {
            int rl = wm * 64 + mi * 16 + (lane >> 2);
            float is0 = sst[rl].y, is1 = sst[rl + 8].y;
            int tok = b * L_ + by * 128 + rl;
            int cc = h * 64 + wn * 16 + ni * 8 + (lane & 3) * 2;
            uint32_t hh, ll;
            split2(cacc[mi][ni][0] * is0, cacc[mi][ni][1] * is0, hh, ll);
            *(uint32_t*)(g_Ch + (size_t)tok * D_ + cc) = hh;
            *(uint32_t*)(g_Cl + (size_t)tok * D_ + cc) = ll;
            split2(cacc[mi][ni][2] * is1, cacc[mi][ni][3] * is1, hh, ll);
            *(uint32_t*)(g_Ch + (size_t)(tok + 8) * D_ + cc) = hh;
            *(uint32_t*)(g_Cl + (size_t)(tok + 8) * D_ + cc) = ll;
        }
}

// ---------------------------------------------------------------------------
extern "C" void kernel_launch(void* const* d_in, const int* in_sizes, int n_in,
                              void* d_out, int out_size)
{
    const float* query = (const float*)d_in[0];
    const float* key_  = (const float*)d_in[1];
    const float* value = (const float*)d_in[2];
    const float* Wq = (const float*)d_in[3];
    const float* bq = (const float*)d_in[4];
    const float* Wk = (const float*)d_in[5];
    const float* bk = (const float*)d_in[6];
    const float* Wv = (const float*)d_in[7];
    const float* bv = (const float*)d_in[8];
    const float* Wo = (const float*)d_in[9];
    const float* bo = (const float*)d_in[10];
    const float* rel_bias = (const float*)d_in[11];
    float* outp = (float*)d_out;

    static float *Vp = nullptr, *Ap = nullptr;
    static float2 *PSp = nullptr;
    static __half *Wth = nullptr, *Wtl = nullptr, *Vth = nullptr, *Vtl = nullptr;
    static __half *Qh = nullptr, *Ql = nullptr, *Kh = nullptr, *Kl = nullptr;
    static __half *Ch = nullptr, *Cl = nullptr, *Xh = nullptr, *Xl = nullptr;
    if (!Vp) {
        cudaGetSymbolAddress((void**)&Vp, g_V);
        cudaGetSymbolAddress((void**)&Ap, g_attn);
        cudaGetSymbolAddress((void**)&PSp, g_pstats);
        cudaGetSymbolAddress((void**)&Wth, g_Wth);
        cudaGetSymbolAddress((void**)&Wtl, g_Wtl);
        cudaGetSymbolAddress((void**)&Vth, g_Vth);
        cudaGetSymbolAddress((void**)&Vtl, g_Vtl);
        cudaGetSymbolAddress((void**)&Qh, g_Qh);
        cudaGetSymbolAddress((void**)&Ql, g_Ql);
        cudaGetSymbolAddress((void**)&Kh, g_Kh);
        cudaGetSymbolAddress((void**)&Kl, g_Kl);
        cudaGetSymbolAddress((void**)&Ch, g_Ch);
        cudaGetSymbolAddress((void**)&Cl, g_Cl);
        cudaGetSymbolAddress((void**)&Xh, g_Xh);
        cudaGetSymbolAddress((void**)&Xl, g_Xl);
        cudaFuncSetAttribute(qkv_proj, cudaFuncAttributeMaxDynamicSharedMemorySize, PJ_SMEM);
        cudaFuncSetAttribute(out_proj, cudaFuncAttributeMaxDynamicSharedMemorySize, PJ_SMEM);
        cudaFuncSetAttribute(scores_stats, cudaFuncAttributeMaxDynamicSharedMemorySize, SC_SMEM);
        cudaFuncSetAttribute(av_flash, cudaFuncAttributeMaxDynamicSharedMemorySize, AF_SMEM);
    }

    float* attn = ((size_t)out_size >= OUT_ELEMS + ATT_ELEMS) ? (outp + OUT_ELEMS) : Ap;
    const size_t WSZ = (size_t)D_ * D_;

    dim3 bT(32, 8);
    wsplit4<<<dim3(D_ / 32, D_ / 32, 4), bT>>>(Wq, Wk, Wv, Wo, Wth, Wtl);
    xsplit<<<dim3((unsigned)((size_t)BL_ * D_ / (256 * 8)), 3), 256>>>(query, key_, value, Xh, Xl);

    dim3 gQKV(D_ / 128, BL_ / 128, 3);
    qkv_proj<<<gQKV, 256, PJ_SMEM>>>(Xh, Xl, Wth, Wtl,
                                     bq, bk, bv, Qh, Ql, Kh, Kl, Vp);

    vsplit<<<dim3(D_ / 32, BL_ / 32), bT>>>(Vp, Vth, Vtl);

    dim3 gScores(L_ / 128, L_ / 128, B_ * H_);
    scores_stats<<<gScores, 256, SC_SMEM>>>(rel_bias, PSp);

    dim3 gAV(L_ / 128, B_ * H_);
    av_flash<<<gAV, 256, AF_SMEM>>>(rel_bias, attn, PSp);

    out_proj<<<dim3(D_ / 128, BL_ / 128), 256, PJ_SMEM>>>(Ch, Cl, Wth + 3 * WSZ, Wtl + 3 * WSZ,
                                                          bo, outp);
}

// round 15
// speedup vs baseline: 1.1427x; 1.1427x over previous
#include <cuda_runtime.h>
#include <cuda_fp16.h>
#include <cstdint>
#include <cstddef>

#define B_   2
#define L_   2048
#define D_   1024
#define H_   16
#define HD_  64
#define BL_  (B_ * L_)
#define NBIAS_ 257
#define STR  40   // smem row stride (halfs) for 32-wide half tiles
#define STR2 72   // smem row stride (halfs) for 64-wide half tiles
#define SRF  36   // smem row stride (floats) for 32-wide fp32 tiles

static const size_t OUT_ELEMS = (size_t)BL_ * D_;
static const size_t ATT_ELEMS = (size_t)B_ * H_ * L_ * (size_t)L_;

// Device-global scratch (allocation-free rule)
__device__ __half g_Xh[3ull * BL_ * D_], g_Xl[3ull * BL_ * D_];  // split inputs q,k,v
__device__ __half g_Qh[(size_t)BL_ * D_], g_Ql[(size_t)BL_ * D_];
__device__ __half g_Kh[(size_t)BL_ * D_], g_Kl[(size_t)BL_ * D_];
__device__ __half g_Ch[(size_t)BL_ * D_], g_Cl[(size_t)BL_ * D_];
__device__ __half g_Wth[4ull * D_ * D_];
__device__ __half g_Wtl[4ull * D_ * D_];
__device__ __half g_Vth[(size_t)BL_ * D_]; // V transposed: [(b*16+h)*64+d][tok]
__device__ __half g_Vtl[(size_t)BL_ * D_];
__device__ float2 g_pstats[(size_t)B_ * H_ * L_ * 16];  // per (row, ktile) partial (m, s)
__device__ float  g_attn[(size_t)B_ * H_ * L_ * (size_t)L_]; // fallback

// ---------------------------------------------------------------------------
// Helpers
// ---------------------------------------------------------------------------
__device__ __forceinline__ uint32_t smem_u32(const void* p) {
    uint32_t a;
    asm("{ .reg .u64 t; cvta.to.shared.u64 t, %1; cvt.u32.u64 %0, t; }" : "=r"(a) : "l"(p));
    return a;
}
__device__ __forceinline__ void cpa16(uint32_t d, const void* s) {
    asm volatile("cp.async.cg.shared.global [%0], [%1], 16;" :: "r"(d), "l"(s));
}
#define CP_COMMIT() asm volatile("cp.async.commit_group;" ::: "memory")
#define CP_WAIT0()  asm volatile("cp.async.wait_group 0;" ::: "memory")
#define CP_WAIT1()  asm volatile("cp.async.wait_group 1;" ::: "memory")

__device__ __forceinline__ void ldsm4(uint32_t r[4], uint32_t addr) {
    asm volatile("ldmatrix.sync.aligned.m8n8.x4.shared.b16 {%0,%1,%2,%3}, [%4];"
                 : "=r"(r[0]), "=r"(r[1]), "=r"(r[2]), "=r"(r[3]) : "r"(addr));
}
__device__ __forceinline__ void ldsm2(uint32_t r[2], uint32_t addr) {
    asm volatile("ldmatrix.sync.aligned.m8n8.x2.shared.b16 {%0,%1}, [%2];"
                 : "=r"(r[0]), "=r"(r[1]) : "r"(addr));
}
__device__ __forceinline__ void mma16816(float c[4], const uint32_t a[4], const uint32_t b[2]) {
    asm volatile("mma.sync.aligned.m16n8k16.row.col.f32.f16.f16.f32 "
                 "{%0,%1,%2,%3}, {%4,%5,%6,%7}, {%8,%9}, {%0,%1,%2,%3};"
                 : "+f"(c[0]), "+f"(c[1]), "+f"(c[2]), "+f"(c[3])
                 : "r"(a[0]), "r"(a[1]), "r"(a[2]), "r"(a[3]), "r"(b[0]), "r"(b[1]));
}

__device__ __forceinline__ uint32_t h2u(__half2 v) { return *reinterpret_cast<uint32_t*>(&v); }

__device__ __forceinline__ void split2(float x, float y, uint32_t& hi, uint32_t& lo) {
    __half h0 = __float2half_rn(x), h1 = __float2half_rn(y);
    __half l0 = __float2half_rn(x - __half2float(h0));
    __half l1 = __float2half_rn(y - __half2float(h1));
    hi = h2u(__halves2half2(h0, h1));
    lo = h2u(__halves2half2(l0, l1));
}

// Async copy of half tile [rows][32] (gs = global row stride, halfs)
__device__ __forceinline__ void cp_half32(const __half* __restrict__ g, int gs,
                                          uint32_t sm, int tid, int rows) {
    int c = tid & 3, r0 = tid >> 2;
    for (int r = r0; r < rows; r += 64)
        cpa16(sm + (uint32_t)(r * STR + c * 8) * 2, g + (size_t)r * gs + c * 8);
}
// Async copy of half tile [rows][64], stride STR2
__device__ __forceinline__ void cp_half64(const __half* __restrict__ g, int gs,
                                          uint32_t sm, int tid, int rows) {
    int c = tid & 7, r0 = tid >> 3;
    for (int r = r0; r < rows; r += 32)
        cpa16(sm + (uint32_t)(r * STR2 + c * 8) * 2, g + (size_t)r * gs + c * 8);
}

// ---------------------------------------------------------------------------
// Prep kernels
// ---------------------------------------------------------------------------
__global__ __launch_bounds__(256) void xsplit(
    const float* __restrict__ X0, const float* __restrict__ X1,
    const float* __restrict__ X2, __half* __restrict__ Xh, __half* __restrict__ Xl)
{
    const float* Xs[3] = {X0, X1, X2};
    const float* X = Xs[blockIdx.y];
    __half* xh = Xh + (size_t)blockIdx.y * BL_ * D_;
    __half* xl = Xl + (size_t)blockIdx.y * BL_ * D_;
    size_t i = ((size_t)blockIdx.x * 256 + threadIdx.x) * 8;
    float4 a = *(const float4*)(X + i);
    float4 b = *(const float4*)(X + i + 4);
    uint32_t h0, l0, h1, l1, h2, l2, h3, l3;
    split2(a.x, a.y, h0, l0);
    split2(a.z, a.w, h1, l1);
    split2(b.x, b.y, h2, l2);
    split2(b.z, b.w, h3, l3);
    *(uint4*)(xh + i) = make_uint4(h0, h1, h2, h3);
    *(uint4*)(xl + i) = make_uint4(l0, l1, l2, l3);
}

__global__ void wsplit4(const float* __restrict__ W0, const float* __restrict__ W1,
                        const float* __restrict__ W2, const float* __restrict__ W3,
                        __half* __restrict__ Th, __half* __restrict__ Tl) {
    __shared__ float t[32][33];
    const float* Ws[4] = {W0, W1, W2, W3};
    const float* W = Ws[blockIdx.z];
    __half* th = Th + (size_t)blockIdx.z * D_ * D_;
    __half* tl = Tl + (size_t)blockIdx.z * D_ * D_;
    int bx = blockIdx.x * 32, by = blockIdx.y * 32;
    int tx = threadIdx.x, ty = threadIdx.y;
    for (int i = ty; i < 32; i += 8)
        t[i][tx] = W[(size_t)(by + i) * D_ + bx + tx];
    __syncthreads();
    for (int i = ty; i < 32; i += 8) {
        float v = t[tx][i];
        __half h = __float2half_rn(v);
        th[(size_t)(bx + i) * D_ + by + tx] = h;
        tl[(size_t)(bx + i) * D_ + by + tx] = __float2half_rn(v - __half2float(h));
    }
}

// ---------------------------------------------------------------------------
// Shared MMA block helper (term-major issue order), A/B stride STR
// ---------------------------------------------------------------------------
#define PJ_PL   (128 * STR)
#define PJ_BUF  (4 * PJ_PL)
#define PJ_SMEM (2 * PJ_BUF * 2)

template <int NI>
__device__ __forceinline__ void mma_block(
    float acc[4][NI][4], const uint32_t pAh, const uint32_t pAl,
    const uint32_t pBh, const uint32_t pBl,
    int wm, int wn, int lane)
{
#pragma unroll
    for (int ks = 0; ks < 32; ks += 16) {
        uint32_t ah[4][4], al[4][4], bh[NI][2], bl[NI][2];
        const uint32_t aoff = (uint32_t)((wm * 64 + (lane & 15)) * STR + ks + (lane >> 4) * 8) * 2;
        const uint32_t boff = (uint32_t)((wn * (8 * NI) + (lane & 7)) * STR + ks + ((lane >> 3) & 1) * 8) * 2;
#pragma unroll
        for (int mi = 0; mi < 4; mi++) {
            ldsm4(ah[mi], pAh + aoff + mi * 16 * STR * 2);
            ldsm4(al[mi], pAl + aoff + mi * 16 * STR * 2);
        }
#pragma unroll
        for (int ni = 0; ni < NI; ni++) {
            ldsm2(bh[ni], pBh + boff + ni * 8 * STR * 2);
            ldsm2(bl[ni], pBl + boff + ni * 8 * STR * 2);
        }
#pragma unroll
        for (int mi = 0; mi < 4; mi++)
#pragma unroll
            for (int ni = 0; ni < NI; ni++) mma16816(acc[mi][ni], ah[mi], bh[ni]);
#pragma unroll
        for (int mi = 0; mi < 4; mi++)
#pragma unroll
            for (int ni = 0; ni < NI; ni++) mma16816(acc[mi][ni], ah[mi], bl[ni]);
#pragma unroll
        for (int mi = 0; mi < 4; mi++)
#pragma unroll
            for (int ni = 0; ni < NI; ni++) mma16816(acc[mi][ni], al[mi], bh[ni]);
    }
}

// ---------------------------------------------------------------------------
// Merged Q/K/V projection: grid (8, 32, 3). z==2 (V) writes transposed split
// halves directly via a smem-staged transpose (vsplit kernel eliminated).
// ---------------------------------------------------------------------------
__global__ __launch_bounds__(256, 2) void qkv_proj(
    const __half* __restrict__ Xh, const __half* __restrict__ Xl,
    const __half* __restrict__ Wth, const __half* __restrict__ Wtl,
    const float* __restrict__ bq, const float* __restrict__ bk,
    const float* __restrict__ bv,
    __half* __restrict__ Qh, __half* __restrict__ Ql,
    __half* __restrict__ Kh, __half* __restrict__ Kl,
    __half* __restrict__ Vth, __half* __restrict__ Vtl)
{
    extern __shared__ __half dsm[];
    const int tid = threadIdx.x, wid = tid >> 5, lane = tid & 31;
    const int wm = wid >> 2, wn = wid & 3;
    const int n0 = blockIdx.x * 128, m0 = blockIdx.y * 128;
    const int z = blockIdx.z;
    const uint32_t sb = smem_u32(dsm);

    const __half* Ahg = Xh + (size_t)z * BL_ * D_;
    const __half* Alg = Xl + (size_t)z * BL_ * D_;
    const __half* Bth = Wth + (size_t)z * D_ * D_;
    const __half* Btl = Wtl + (size_t)z * D_ * D_;
    const float* bias = (z == 0) ? bq : (z == 1) ? bk : bv;

    float acc[4][4][4];
#pragma unroll
    for (int i = 0; i < 4; i++)
#pragma unroll
        for (int j = 0; j < 4; j++)
#pragma unroll
            for (int f = 0; f < 4; f++) acc[i][j][f] = 0.0f;

    const int NT = D_ / 32;

    auto stage = [&](int kt, int buf) {
        const int k0 = kt * 32;
        uint32_t ub = sb + (uint32_t)(buf * PJ_BUF) * 2;
        cp_half32(Ahg + (size_t)m0 * D_ + k0, D_, ub + 0 * PJ_PL * 2, tid, 128);
        cp_half32(Alg + (size_t)m0 * D_ + k0, D_, ub + 1 * PJ_PL * 2, tid, 128);
        cp_half32(Bth + (size_t)n0 * D_ + k0, D_, ub + 2 * PJ_PL * 2, tid, 128);
        cp_half32(Btl + (size_t)n0 * D_ + k0, D_, ub + 3 * PJ_PL * 2, tid, 128);
        CP_COMMIT();
    };

    stage(0, 0);
    stage(1, 1);

    for (int kt = 0; kt < NT; kt++) {
        if (kt + 1 < NT) { CP_WAIT1(); } else { CP_WAIT0(); }
        __syncthreads();
        const int buf = kt & 1;
        mma_block<4>(acc,
                     sb + (uint32_t)(buf * PJ_BUF + 0 * PJ_PL) * 2,
                     sb + (uint32_t)(buf * PJ_BUF + 1 * PJ_PL) * 2,
                     sb + (uint32_t)(buf * PJ_BUF + 2 * PJ_PL) * 2,
                     sb + (uint32_t)(buf * PJ_BUF + 3 * PJ_PL) * 2,
                     wm, wn, lane);
        __syncthreads();
        if (kt + 2 < NT) stage(kt + 2, buf);
    }

    if (z != 2) {
#pragma unroll
        for (int mi = 0; mi < 4; mi++)
#pragma unroll
            for (int ni = 0; ni < 4; ni++) {
                int r = m0 + wm * 64 + mi * 16 + (lane >> 2);
                int cc = n0 + wn * 32 + ni * 8 + (lane & 3) * 2;
                float b0 = bias[cc], b1 = bias[cc + 1];
                float v0 = acc[mi][ni][0] + b0, v1 = acc[mi][ni][1] + b1;
                float v2 = acc[mi][ni][2] + b0, v3 = acc[mi][ni][3] + b1;
                __half* Ch = (z == 0) ? Qh : Kh;
                __half* Cl = (z == 0) ? Ql : Kl;
                uint32_t h, l;
                split2(v0, v1, h, l);
                *(uint32_t*)(Ch + (size_t)r * D_ + cc) = h;
                *(uint32_t*)(Cl + (size_t)r * D_ + cc) = l;
                split2(v2, v3, h, l);
                *(uint32_t*)(Ch + (size_t)(r + 8) * D_ + cc) = h;
                *(uint32_t*)(Cl + (size_t)(r + 8) * D_ + cc) = l;
            }
    } else {
        // V: stage tile [feature][token] in smem, then write transposed halves.
        float* stg = (float*)dsm;   // [128][132] floats = 67584 B <= 80 KB
#pragma unroll
        for (int mi = 0; mi < 4; mi++)
#pragma unroll
            for (int ni = 0; ni < 4; ni++) {
                int tloc = wm * 64 + mi * 16 + (lane >> 2);
                int cloc = wn * 32 + ni * 8 + (lane & 3) * 2;
                float b0 = bias[n0 + cloc], b1 = bias[n0 + cloc + 1];
                stg[(cloc + 0) * 132 + tloc]     = acc[mi][ni][0] + b0;
                stg[(cloc + 1) * 132 + tloc]     = acc[mi][ni][1] + b1;
                stg[(cloc + 0) * 132 + tloc + 8] = acc[mi][ni][2] + b0;
                stg[(cloc + 1) * 132 + tloc + 8] = acc[mi][ni][3] + b1;
            }
        __syncthreads();
        const int fl = tid & 127, seg = tid >> 7;   // feature-local, token half
        const int fg = n0 + fl;
        const int hh_ = fg >> 6, dd = fg & 63;
        const int bb = m0 >> 11;
        const int tokin = (m0 & (L_ - 1)) + seg * 64;
        __half* dh = Vth + (((size_t)(bb * H_ + hh_)) * 64 + dd) * L_ + tokin;
        __half* dl = Vtl + (((size_t)(bb * H_ + hh_)) * 64 + dd) * L_ + tokin;
#pragma unroll
        for (int i = 0; i < 64; i += 4) {
            float4 v = *(const float4*)&stg[fl * 132 + seg * 64 + i];
            uint32_t h0, l0, h1, l1;
            split2(v.x, v.y, h0, l0);
            split2(v.z, v.w, h1, l1);
            *(uint2*)(dh + i) = make_uint2(h0, h1);
            *(uint2*)(dl + i) = make_uint2(l0, l1);
        }
    }
}

// ---------------------------------------------------------------------------
// Output projection: ctx halves @ Wo + bo -> fp32 out.
// ---------------------------------------------------------------------------
__global__ __launch_bounds__(256, 2) void out_proj(
    const __half* __restrict__ Ahg, const __half* __restrict__ Alg,
    const __half* __restrict__ Bth, const __half* __restrict__ Btl,
    const float* __restrict__ bias, float* __restrict__ C32)
{
    extern __shared__ __half dsm[];
    const int tid = threadIdx.x, wid = tid >> 5, lane = tid & 31;
    const int wm = wid >> 2, wn = wid & 3;
    const int n0 = blockIdx.x * 128, m0 = blockIdx.y * 128;
    const uint32_t sb = smem_u32(dsm);

    float acc[4][4][4];
#pragma unroll
    for (int i = 0; i < 4; i++)
#pragma unroll
        for (int j = 0; j < 4; j++)
#pragma unroll
            for (int f = 0; f < 4; f++) acc[i][j][f] = 0.0f;

    const int NT = D_ / 32;

    auto stage = [&](int kt, int buf) {
        const int k0 = kt * 32;
        uint32_t ub = sb + (uint32_t)(buf * PJ_BUF) * 2;
        cp_half32(Ahg + (size_t)m0 * D_ + k0, D_, ub + 0 * PJ_PL * 2, tid, 128);
        cp_half32(Alg + (size_t)m0 * D_ + k0, D_, ub + 1 * PJ_PL * 2, tid, 128);
        cp_half32(Bth + (size_t)n0 * D_ + k0, D_, ub + 2 * PJ_PL * 2, tid, 128);
        cp_half32(Btl + (size_t)n0 * D_ + k0, D_, ub + 3 * PJ_PL * 2, tid, 128);
        CP_COMMIT();
    };

    stage(0, 0);
    stage(1, 1);

    for (int kt = 0; kt < NT; kt++) {
        if (kt + 1 < NT) { CP_WAIT1(); } else { CP_WAIT0(); }
        __syncthreads();
        const int buf = kt & 1;
        mma_block<4>(acc,
                     sb + (uint32_t)(buf * PJ_BUF + 0 * PJ_PL) * 2,
                     sb + (uint32_t)(buf * PJ_BUF + 1 * PJ_PL) * 2,
                     sb + (uint32_t)(buf * PJ_BUF + 2 * PJ_PL) * 2,
                     sb + (uint32_t)(buf * PJ_BUF + 3 * PJ_PL) * 2,
                     wm, wn, lane);
        __syncthreads();
        if (kt + 2 < NT) stage(kt + 2, buf);
    }

#pragma unroll
    for (int mi = 0; mi < 4; mi++)
#pragma unroll
        for (int ni = 0; ni < 4; ni++) {
            int r = m0 + wm * 64 + mi * 16 + (lane >> 2);
            int cc = n0 + wn * 32 + ni * 8 + (lane & 3) * 2;
            float b0 = bias[cc], b1 = bias[cc + 1];
            *(float2*)(C32 + (size_t)r * D_ + cc) =
                make_float2(acc[mi][ni][0] + b0, acc[mi][ni][1] + b1);
            *(float2*)(C32 + (size_t)(r + 8) * D_ + cc) =
                make_float2(acc[mi][ni][2] + b0, acc[mi][ni][3] + b1);
        }
}

// ---------------------------------------------------------------------------
// Scores: whole K=64 resident; term-major MMA; epilogue emits S + per-tile
// partial softmax stats. launch_bounds(256,2) keeps regs at 128 / occ 2 CTAs.
// ---------------------------------------------------------------------------
#define SC_PL   (128 * STR2)
#define SC_SMEM (4 * SC_PL * 2)

__global__ __launch_bounds__(256, 2) void scores_tc(
    const float* __restrict__ rel_bias, float* __restrict__ attn,
    float2* __restrict__ pstats)
{
    extern __shared__ __half dsm[];
    __shared__ float sbias[NBIAS_];

    const int tid = threadIdx.x, wid = tid >> 5, lane = tid & 31;
    const int wm = wid >> 2, wn = wid & 3;
    const int bx = blockIdx.x, by = blockIdx.y, bh_ = blockIdx.z;
    const int b = bh_ >> 4, h = bh_ & 15;
    const uint32_t sb = smem_u32(dsm);

    const size_t qb = (size_t)(b * L_ + by * 128) * D_ + h * HD_;
    const size_t kb = (size_t)(b * L_ + bx * 128) * D_ + h * HD_;

    cp_half64(g_Qh + qb, D_, sb + 0u * SC_PL * 2, tid, 128);
    cp_half64(g_Ql + qb, D_, sb + 1u * SC_PL * 2, tid, 128);
    cp_half64(g_Kh + kb, D_, sb + 2u * SC_PL * 2, tid, 128);
    cp_half64(g_Kl + kb, D_, sb + 3u * SC_PL * 2, tid, 128);
    CP_COMMIT();

    for (int i = tid; i < NBIAS_; i += 256) sbias[i] = rel_bias[i * H_ + h];

    float acc[4][4][4];
#pragma unroll
    for (int i = 0; i < 4; i++)
#pragma unroll
        for (int j = 0; j < 4; j++)
#pragma unroll
            for (int f = 0; f < 4; f++) acc[i][j][f] = 0.0f;

    CP_WAIT0();
    __syncthreads();

    const uint32_t pAh = sb + 0u * SC_PL * 2, pAl = sb + 1u * SC_PL * 2;
    const uint32_t pBh = sb + 2u * SC_PL * 2, pBl = sb + 3u * SC_PL * 2;
#pragma unroll
    for (int ks = 0; ks < 64; ks += 16) {
        uint32_t ah[4][4], al[4][4], bh[4][2], bl[4][2];
        const uint32_t aoff = (uint32_t)((wm * 64 + (lane & 15)) * STR2 + ks + (lane >> 4) * 8) * 2;
        const uint32_t boff = (uint32_t)((wn * 32 + (lane & 7)) * STR2 + ks + ((lane >> 3) & 1) * 8) * 2;
#pragma unroll
        for (int mi = 0; mi < 4; mi++) {
            ldsm4(ah[mi], pAh + aoff + mi * 16 * STR2 * 2);
            ldsm4(al[mi], pAl + aoff + mi * 16 * STR2 * 2);
        }
#pragma unroll
        for (int ni = 0; ni < 4; ni++) {
            ldsm2(bh[ni], pBh + boff + ni * 8 * STR2 * 2);
            ldsm2(bl[ni], pBl + boff + ni * 8 * STR2 * 2);
        }
#pragma unroll
        for (int mi = 0; mi < 4; mi++)
#pragma unroll
            for (int ni = 0; ni < 4; ni++) mma16816(acc[mi][ni], ah[mi], bh[ni]);
#pragma unroll
        for (int mi = 0; mi < 4; mi++)
#pragma unroll
            for (int ni = 0; ni < 4; ni++) mma16816(acc[mi][ni], ah[mi], bl[ni]);
#pragma unroll
        for (int mi = 0; mi < 4; mi++)
#pragma unroll
            for (int ni = 0; ni < 4; ni++) mma16816(acc[mi][ni], al[mi], bh[ni]);
    }

    __syncthreads();
    float* red_m = (float*)dsm;          // [128][4]
    float* red_s = (float*)dsm + 512;    // [128][4]

    float* base = attn + (size_t)bh_ * L_ * L_;
#pragma unroll
    for (int mi = 0; mi < 4; mi++)
#pragma unroll
        for (int rh = 0; rh < 2; rh++) {
            int rl = wm * 64 + mi * 16 + rh * 8 + (lane >> 2);
            int q = by * 128 + rl;
            float v[8];
#pragma unroll
            for (int ni = 0; ni < 4; ni++) {
                int kc = bx * 128 + wn * 32 + ni * 8 + (lane & 3) * 2;
                int rel0 = kc - q;     rel0 = rel0 < -128 ? -128 : (rel0 > 128 ? 128 : rel0);
                int rel1 = kc + 1 - q; rel1 = rel1 < -128 ? -128 : (rel1 > 128 ? 128 : rel1);
                v[ni * 2 + 0] = acc[mi][ni][rh * 2 + 0] * 0.125f + sbias[rel0 + 128];
                v[ni * 2 + 1] = acc[mi][ni][rh * 2 + 1] * 0.125f + sbias[rel1 + 128];
                *(float2*)(base + (size_t)q * L_ + kc) = make_float2(v[ni * 2], v[ni * 2 + 1]);
            }
            float m = v[0];
#pragma unroll
            for (int i = 1; i < 8; i++) m = fmaxf(m, v[i]);
            m = fmaxf(m, __shfl_xor_sync(0xffffffffu, m, 1));
            m = fmaxf(m, __shfl_xor_sync(0xffffffffu, m, 2));
            float s = 0.0f;
#pragma unroll
            for (int i = 0; i < 8; i++) s += __expf(v[i] - m);
            s += __shfl_xor_sync(0xffffffffu, s, 1);
            s += __shfl_xor_sync(0xffffffffu, s, 2);
            if ((lane & 3) == 0) {
                red_m[rl * 4 + wn] = m;
                red_s[rl * 4 + wn] = s;
            }
        }
    __syncthreads();
    if (tid < 128) {
        float m0 = red_m[tid * 4 + 0], m1 = red_m[tid * 4 + 1];
        float m2 = red_m[tid * 4 + 2], m3 = red_m[tid * 4 + 3];
        float M = fmaxf(fmaxf(m0, m1), fmaxf(m2, m3));
        float S = red_s[tid * 4 + 0] * __expf(m0 - M) + red_s[tid * 4 + 1] * __expf(m1 - M)
                + red_s[tid * 4 + 2] * __expf(m2 - M) + red_s[tid * 4 + 3] * __expf(m3 - M);
        pstats[((size_t)bh_ * L_ + by * 128 + tid) * 16 + bx] = make_float2(M, S);
    }
}

// ---------------------------------------------------------------------------
// Fused softmax + AV. Prologue combines 16 partial stats per row in-kernel.
// ---------------------------------------------------------------------------
#define AV_OFF_AH 36864
#define AV_OFF_AL 47104
#define AV_OFF_V  57344
#define AV_OFF_ST 77824
#define AV_SMEM   78848

__global__ __launch_bounds__(256, 2) void av_fused(
    float* __restrict__ attn, const float2* __restrict__ pstats)
{
    extern __shared__ char dsmc[];
    float*  Sbuf = (float*)dsmc;
    __half* Ahp  = (__half*)(dsmc + AV_OFF_AH);
    __half* Alp  = (__half*)(dsmc + AV_OFF_AL);
    float2* sst  = (float2*)(dsmc + AV_OFF_ST);

    const int tid = threadIdx.x, wid = tid >> 5, lane = tid & 31;
    const int wm = wid >> 2, wn = wid & 3;
    const int by = blockIdx.x, bh_ = blockIdx.y;
    const int b = bh_ >> 4, h = bh_ & 15;
    const uint32_t sb = smem_u32(dsmc);
    const uint32_t uAh = sb + AV_OFF_AH, uAl = sb + AV_OFF_AL, uV = sb + AV_OFF_V;

    const size_t pb = ((size_t)bh_ * L_ + by * 128) * L_;
    const size_t vbase = (size_t)bh_ * 64 * L_;

    if (tid < 128) {
        const float2* p = pstats + ((size_t)bh_ * L_ + by * 128 + tid) * 16;
        float2 v[16];
#pragma unroll
        for (int i = 0; i < 16; i++) v[i] = p[i];
        float M = v[0].x;
#pragma unroll
        for (int i = 1; i < 16; i++) M = fmaxf(M, v[i].x);
        float S = 0.0f;
#pragma unroll
        for (int i = 0; i < 16; i++) S += v[i].y * __expf(v[i].x - M);
        sst[tid] = make_float2(M, 1.0f / S);
    }

    float acc[4][2][4];
#pragma unroll
    for (int i = 0; i < 4; i++)
#pragma unroll
        for (int j = 0; j < 2; j++)
#pragma unroll
            for (int f = 0; f < 4; f++) acc[i][j][f] = 0.0f;

    const int NT = L_ / 32;
    const int c8 = tid & 7, r32 = tid >> 3;

    auto stage = [&](int kt, int buf) {
        const int k0 = kt * 32;
        for (int r = r32; r < 128; r += 32)
            cpa16(sb + (uint32_t)((buf * 128 + r) * SRF + c8 * 4) * 4,
                  attn + pb + (size_t)r * L_ + k0 + c8 * 4);
        cp_half32(g_Vth + vbase + k0, L_, uV + (uint32_t)buf * 10240, tid, 64);
        cp_half32(g_Vtl + vbase + k0, L_, uV + (uint32_t)buf * 10240 + 5120, tid, 64);
        CP_COMMIT();
    };

    stage(0, 0);
    stage(1, 1);

    for (int kt = 0; kt < NT; kt++) {
        if (kt + 1 < NT) { CP_WAIT1(); } else { CP_WAIT0(); }
        __syncthreads();
        const int buf = kt & 1;
        const int k0 = kt * 32;

        for (int r = r32; r < 128; r += 32) {
            float4 v = *(const float4*)(Sbuf + (buf * 128 + r) * SRF + c8 * 4);
            float2 ms = sst[r];
            float p0 = __expf(v.x - ms.x);
            float p1 = __expf(v.y - ms.x);
            float p2 = __expf(v.z - ms.x);
            float p3 = __expf(v.w - ms.x);
            *(float4*)(attn + pb + (size_t)r * L_ + k0 + c8 * 4) =
                make_float4(p0 * ms.y, p1 * ms.y, p2 * ms.y, p3 * ms.y);
            uint32_t h0, l0, h1, l1;
            split2(p0, p1, h0, l0);
            split2(p2, p3, h1, l1);
            *(uint2*)(Ahp + r * STR + c8 * 4) = make_uint2(h0, h1);
            *(uint2*)(Alp + r * STR + c8 * 4) = make_uint2(l0, l1);
        }
        __syncthreads();

        const uint32_t pBh = uV + (uint32_t)buf * 10240;
        const uint32_t pBl = pBh + 5120;
        mma_block<2>(acc, uAh, uAl, pBh, pBl, wm, wn, lane);
        __syncthreads();
        if (kt + 2 < NT) stage(kt + 2, buf);
    }

#pragma unroll
    for (int mi = 0; mi < 4; mi++)
#pragma unroll
        for (int ni = 0; ni < 2; ni++) {
            int rl = wm * 64 + mi * 16 + (lane >> 2);
            float is0 = sst[rl].y, is1 = sst[rl + 8].y;
            int tok = b * L_ + by * 128 + rl;
            int cc = h * 64 + wn * 16 + ni * 8 + (lane & 3) * 2;
            uint32_t hh, ll;
            split2(acc[mi][ni][0] * is0, acc[mi][ni][1] * is0, hh, ll);
            *(uint32_t*)(g_Ch + (size_t)tok * D_ + cc) = hh;
            *(uint32_t*)(g_Cl + (size_t)tok * D_ + cc) = ll;
            split2(acc[mi][ni][2] * is1, acc[mi][ni][3] * is1, hh, ll);
            *(uint32_t*)(g_Ch + (size_t)(tok + 8) * D_ + cc) = hh;
            *(uint32_t*)(g_Cl + (size_t)(tok + 8) * D_ + cc) = ll;
        }
}

// ---------------------------------------------------------------------------
extern "C" void kernel_launch(void* const* d_in, const int* in_sizes, int n_in,
                              void* d_out, int out_size)
{
    const float* query = (const float*)d_in[0];
    const float* key_  = (const float*)d_in[1];
    const float* value = (const float*)d_in[2];
    const float* Wq = (const float*)d_in[3];
    const float* bq = (const float*)d_in[4];
    const float* Wk = (const float*)d_in[5];
    const float* bk = (const float*)d_in[6];
    const float* Wv = (const float*)d_in[7];
    const float* bv = (const float*)d_in[8];
    const float* Wo = (const float*)d_in[9];
    const float* bo = (const float*)d_in[10];
    const float* rel_bias = (const float*)d_in[11];
    float* outp = (float*)d_out;

    static float *Ap = nullptr;
    static float2 *PSp = nullptr;
    static __half *Wth = nullptr, *Wtl = nullptr, *Vth = nullptr, *Vtl = nullptr;
    static __half *Qh = nullptr, *Ql = nullptr, *Kh = nullptr, *Kl = nullptr;
    static __half *Ch = nullptr, *Cl = nullptr, *Xh = nullptr, *Xl = nullptr;
    if (!Ap) {
        cudaGetSymbolAddress((void**)&Ap, g_attn);
        cudaGetSymbolAddress((void**)&PSp, g_pstats);
        cudaGetSymbolAddress((void**)&Wth, g_Wth);
        cudaGetSymbolAddress((void**)&Wtl, g_Wtl);
        cudaGetSymbolAddress((void**)&Vth, g_Vth);
        cudaGetSymbolAddress((void**)&Vtl, g_Vtl);
        cudaGetSymbolAddress((void**)&Qh, g_Qh);
        cudaGetSymbolAddress((void**)&Ql, g_Ql);
        cudaGetSymbolAddress((void**)&Kh, g_Kh);
        cudaGetSymbolAddress((void**)&Kl, g_Kl);
        cudaGetSymbolAddress((void**)&Ch, g_Ch);
        cudaGetSymbolAddress((void**)&Cl, g_Cl);
        cudaGetSymbolAddress((void**)&Xh, g_Xh);
        cudaGetSymbolAddress((void**)&Xl, g_Xl);
        cudaFuncSetAttribute(qkv_proj, cudaFuncAttributeMaxDynamicSharedMemorySize, PJ_SMEM);
        cudaFuncSetAttribute(out_proj, cudaFuncAttributeMaxDynamicSharedMemorySize, PJ_SMEM);
        cudaFuncSetAttribute(scores_tc, cudaFuncAttributeMaxDynamicSharedMemorySize, SC_SMEM);
        cudaFuncSetAttribute(av_fused, cudaFuncAttributeMaxDynamicSharedMemorySize, AV_SMEM);
    }

    float* attn = ((size_t)out_size >= OUT_ELEMS + ATT_ELEMS) ? (outp + OUT_ELEMS) : Ap;
    const size_t WSZ = (size_t)D_ * D_;

    dim3 bT(32, 8);
    wsplit4<<<dim3(D_ / 32, D_ / 32, 4), bT>>>(Wq, Wk, Wv, Wo, Wth, Wtl);
    xsplit<<<dim3((unsigned)((size_t)BL_ * D_ / (256 * 8)), 3), 256>>>(query, key_, value, Xh, Xl);

    dim3 gQKV(D_ / 128, BL_ / 128, 3);   // (8, 32, 3)
    qkv_proj<<<gQKV, 256, PJ_SMEM>>>(Xh, Xl, Wth, Wtl,
                                     bq, bk, bv, Qh, Ql, Kh, Kl, Vth, Vtl);

    dim3 gScores(L_ / 128, L_ / 128, B_ * H_);  // (16, 16, 32)
    scores_tc<<<gScores, 256, SC_SMEM>>>(rel_bias, attn, PSp);

    dim3 gAV(L_ / 128, B_ * H_);       // (16, 32)
    av_fused<<<gAV, 256, AV_SMEM>>>(attn, PSp);

    out_proj<<<dim3(D_ / 128, BL_ / 128), 256, PJ_SMEM>>>(Ch, Cl, Wth + 3 * WSZ, Wtl + 3 * WSZ,
                                                          bo, outp);
}

// round 16
// speedup vs baseline: 1.1793x; 1.0321x over previous
#include <cuda_runtime.h>
#include <cuda_fp16.h>
#include <cstdint>
#include <cstddef>

#define B_   2
#define L_   2048
#define D_   1024
#define H_   16
#define HD_  64
#define BL_  (B_ * L_)
#define NBIAS_ 257
#define STR  40   // smem row stride (halfs) for 32-wide half tiles
#define STR2 72   // smem row stride (halfs) for 64-wide half tiles
#define SRF  36   // smem row stride (floats) for 32-wide fp32 tiles

static const size_t OUT_ELEMS = (size_t)BL_ * D_;
static const size_t ATT_ELEMS = (size_t)B_ * H_ * L_ * (size_t)L_;

// Device-global scratch (allocation-free rule)
__device__ __half g_Xh[3ull * BL_ * D_], g_Xl[3ull * BL_ * D_];  // split inputs q,k,v
__device__ __half g_Qh[(size_t)BL_ * D_], g_Ql[(size_t)BL_ * D_];
__device__ __half g_Kh[(size_t)BL_ * D_], g_Kl[(size_t)BL_ * D_];
__device__ __half g_Ch[(size_t)BL_ * D_], g_Cl[(size_t)BL_ * D_];
__device__ __half g_Wth[4ull * D_ * D_];
__device__ __half g_Wtl[4ull * D_ * D_];
__device__ __half g_Vth[(size_t)BL_ * D_]; // V transposed: [(b*16+h)*64+d][tok]
__device__ __half g_Vtl[(size_t)BL_ * D_];
__device__ float2 g_pstats[(size_t)B_ * H_ * L_ * 16];  // per (row, ktile) partial (m, s)
__device__ float  g_attn[(size_t)B_ * H_ * L_ * (size_t)L_]; // fallback

// ---------------------------------------------------------------------------
// Helpers
// ---------------------------------------------------------------------------
__device__ __forceinline__ uint32_t smem_u32(const void* p) {
    uint32_t a;
    asm("{ .reg .u64 t; cvta.to.shared.u64 t, %1; cvt.u32.u64 %0, t; }" : "=r"(a) : "l"(p));
    return a;
}
__device__ __forceinline__ void cpa16(uint32_t d, const void* s) {
    asm volatile("cp.async.cg.shared.global [%0], [%1], 16;" :: "r"(d), "l"(s));
}
#define CP_COMMIT() asm volatile("cp.async.commit_group;" ::: "memory")
#define CP_WAIT0()  asm volatile("cp.async.wait_group 0;" ::: "memory")
#define CP_WAIT1()  asm volatile("cp.async.wait_group 1;" ::: "memory")

__device__ __forceinline__ void ldsm4(uint32_t r[4], uint32_t addr) {
    asm volatile("ldmatrix.sync.aligned.m8n8.x4.shared.b16 {%0,%1,%2,%3}, [%4];"
                 : "=r"(r[0]), "=r"(r[1]), "=r"(r[2]), "=r"(r[3]) : "r"(addr));
}
__device__ __forceinline__ void ldsm2(uint32_t r[2], uint32_t addr) {
    asm volatile("ldmatrix.sync.aligned.m8n8.x2.shared.b16 {%0,%1}, [%2];"
                 : "=r"(r[0]), "=r"(r[1]) : "r"(addr));
}
__device__ __forceinline__ void mma16816(float c[4], const uint32_t a[4], const uint32_t b[2]) {
    asm volatile("mma.sync.aligned.m16n8k16.row.col.f32.f16.f16.f32 "
                 "{%0,%1,%2,%3}, {%4,%5,%6,%7}, {%8,%9}, {%0,%1,%2,%3};"
                 : "+f"(c[0]), "+f"(c[1]), "+f"(c[2]), "+f"(c[3])
                 : "r"(a[0]), "r"(a[1]), "r"(a[2]), "r"(a[3]), "r"(b[0]), "r"(b[1]));
}

__device__ __forceinline__ uint32_t h2u(__half2 v) { return *reinterpret_cast<uint32_t*>(&v); }

__device__ __forceinline__ void split2(float x, float y, uint32_t& hi, uint32_t& lo) {
    __half h0 = __float2half_rn(x), h1 = __float2half_rn(y);
    __half l0 = __float2half_rn(x - __half2float(h0));
    __half l1 = __float2half_rn(y - __half2float(h1));
    hi = h2u(__halves2half2(h0, h1));
    lo = h2u(__halves2half2(l0, l1));
}

// Async copy of half tile [rows][32] (gs = global row stride, halfs)
__device__ __forceinline__ void cp_half32(const __half* __restrict__ g, int gs,
                                          uint32_t sm, int tid, int rows) {
    int c = tid & 3, r0 = tid >> 2;
    for (int r = r0; r < rows; r += 64)
        cpa16(sm + (uint32_t)(r * STR + c * 8) * 2, g + (size_t)r * gs + c * 8);
}
// Async copy of half tile [rows][64], stride STR2
__device__ __forceinline__ void cp_half64(const __half* __restrict__ g, int gs,
                                          uint32_t sm, int tid, int rows) {
    int c = tid & 7, r0 = tid >> 3;
    for (int r = r0; r < rows; r += 32)
        cpa16(sm + (uint32_t)(r * STR2 + c * 8) * 2, g + (size_t)r * gs + c * 8);
}

// ---------------------------------------------------------------------------
// Prep kernels
// ---------------------------------------------------------------------------
__global__ __launch_bounds__(256) void xsplit(
    const float* __restrict__ X0, const float* __restrict__ X1,
    const float* __restrict__ X2, __half* __restrict__ Xh, __half* __restrict__ Xl)
{
    const float* Xs[3] = {X0, X1, X2};
    const float* X = Xs[blockIdx.y];
    __half* xh = Xh + (size_t)blockIdx.y * BL_ * D_;
    __half* xl = Xl + (size_t)blockIdx.y * BL_ * D_;
    size_t i = ((size_t)blockIdx.x * 256 + threadIdx.x) * 8;
    float4 a = *(const float4*)(X + i);
    float4 b = *(const float4*)(X + i + 4);
    uint32_t h0, l0, h1, l1, h2, l2, h3, l3;
    split2(a.x, a.y, h0, l0);
    split2(a.z, a.w, h1, l1);
    split2(b.x, b.y, h2, l2);
    split2(b.z, b.w, h3, l3);
    *(uint4*)(xh + i) = make_uint4(h0, h1, h2, h3);
    *(uint4*)(xl + i) = make_uint4(l0, l1, l2, l3);
}

__global__ void wsplit4(const float* __restrict__ W0, const float* __restrict__ W1,
                        const float* __restrict__ W2, const float* __restrict__ W3,
                        __half* __restrict__ Th, __half* __restrict__ Tl) {
    __shared__ float t[32][33];
    const float* Ws[4] = {W0, W1, W2, W3};
    const float* W = Ws[blockIdx.z];
    __half* th = Th + (size_t)blockIdx.z * D_ * D_;
    __half* tl = Tl + (size_t)blockIdx.z * D_ * D_;
    int bx = blockIdx.x * 32, by = blockIdx.y * 32;
    int tx = threadIdx.x, ty = threadIdx.y;
    for (int i = ty; i < 32; i += 8)
        t[i][tx] = W[(size_t)(by + i) * D_ + bx + tx];
    __syncthreads();
    for (int i = ty; i < 32; i += 8) {
        float v = t[tx][i];
        __half h = __float2half_rn(v);
        th[(size_t)(bx + i) * D_ + by + tx] = h;
        tl[(size_t)(bx + i) * D_ + by + tx] = __float2half_rn(v - __half2float(h));
    }
}

// ---------------------------------------------------------------------------
// Shared MMA block helper (term-major issue order), A/B stride STR
// ---------------------------------------------------------------------------
#define PJ_PL   (128 * STR)
#define PJ_BUF  (4 * PJ_PL)
#define PJ_SMEM (2 * PJ_BUF * 2)

template <int NI>
__device__ __forceinline__ void mma_block(
    float acc[4][NI][4], const uint32_t pAh, const uint32_t pAl,
    const uint32_t pBh, const uint32_t pBl,
    int wm, int wn, int lane)
{
#pragma unroll
    for (int ks = 0; ks < 32; ks += 16) {
        uint32_t ah[4][4], al[4][4], bh[NI][2], bl[NI][2];
        const uint32_t aoff = (uint32_t)((wm * 64 + (lane & 15)) * STR + ks + (lane >> 4) * 8) * 2;
        const uint32_t boff = (uint32_t)((wn * (8 * NI) + (lane & 7)) * STR + ks + ((lane >> 3) & 1) * 8) * 2;
#pragma unroll
        for (int mi = 0; mi < 4; mi++) {
            ldsm4(ah[mi], pAh + aoff + mi * 16 * STR * 2);
            ldsm4(al[mi], pAl + aoff + mi * 16 * STR * 2);
        }
#pragma unroll
        for (int ni = 0; ni < NI; ni++) {
            ldsm2(bh[ni], pBh + boff + ni * 8 * STR * 2);
            ldsm2(bl[ni], pBl + boff + ni * 8 * STR * 2);
        }
#pragma unroll
        for (int mi = 0; mi < 4; mi++)
#pragma unroll
            for (int ni = 0; ni < NI; ni++) mma16816(acc[mi][ni], ah[mi], bh[ni]);
#pragma unroll
        for (int mi = 0; mi < 4; mi++)
#pragma unroll
            for (int ni = 0; ni < NI; ni++) mma16816(acc[mi][ni], ah[mi], bl[ni]);
#pragma unroll
        for (int mi = 0; mi < 4; mi++)
#pragma unroll
            for (int ni = 0; ni < NI; ni++) mma16816(acc[mi][ni], al[mi], bh[ni]);
    }
}

// ---------------------------------------------------------------------------
// Merged Q/K/V projection: grid (8, 32, 3). z==2 (V) writes transposed split
// halves directly via a smem-staged transpose.
// ---------------------------------------------------------------------------
__global__ __launch_bounds__(256, 2) void qkv_proj(
    const __half* __restrict__ Xh, const __half* __restrict__ Xl,
    const __half* __restrict__ Wth, const __half* __restrict__ Wtl,
    const float* __restrict__ bq, const float* __restrict__ bk,
    const float* __restrict__ bv,
    __half* __restrict__ Qh, __half* __restrict__ Ql,
    __half* __restrict__ Kh, __half* __restrict__ Kl,
    __half* __restrict__ Vth, __half* __restrict__ Vtl)
{
    extern __shared__ __half dsm[];
    const int tid = threadIdx.x, wid = tid >> 5, lane = tid & 31;
    const int wm = wid >> 2, wn = wid & 3;
    const int n0 = blockIdx.x * 128, m0 = blockIdx.y * 128;
    const int z = blockIdx.z;
    const uint32_t sb = smem_u32(dsm);

    const __half* Ahg = Xh + (size_t)z * BL_ * D_;
    const __half* Alg = Xl + (size_t)z * BL_ * D_;
    const __half* Bth = Wth + (size_t)z * D_ * D_;
    const __half* Btl = Wtl + (size_t)z * D_ * D_;
    const float* bias = (z == 0) ? bq : (z == 1) ? bk : bv;

    float acc[4][4][4];
#pragma unroll
    for (int i = 0; i < 4; i++)
#pragma unroll
        for (int j = 0; j < 4; j++)
#pragma unroll
            for (int f = 0; f < 4; f++) acc[i][j][f] = 0.0f;

    const int NT = D_ / 32;

    auto stage = [&](int kt, int buf) {
        const int k0 = kt * 32;
        uint32_t ub = sb + (uint32_t)(buf * PJ_BUF) * 2;
        cp_half32(Ahg + (size_t)m0 * D_ + k0, D_, ub + 0 * PJ_PL * 2, tid, 128);
        cp_half32(Alg + (size_t)m0 * D_ + k0, D_, ub + 1 * PJ_PL * 2, tid, 128);
        cp_half32(Bth + (size_t)n0 * D_ + k0, D_, ub + 2 * PJ_PL * 2, tid, 128);
        cp_half32(Btl + (size_t)n0 * D_ + k0, D_, ub + 3 * PJ_PL * 2, tid, 128);
        CP_COMMIT();
    };

    stage(0, 0);
    stage(1, 1);

    for (int kt = 0; kt < NT; kt++) {
        if (kt + 1 < NT) { CP_WAIT1(); } else { CP_WAIT0(); }
        __syncthreads();
        const int buf = kt & 1;
        mma_block<4>(acc,
                     sb + (uint32_t)(buf * PJ_BUF + 0 * PJ_PL) * 2,
                     sb + (uint32_t)(buf * PJ_BUF + 1 * PJ_PL) * 2,
                     sb + (uint32_t)(buf * PJ_BUF + 2 * PJ_PL) * 2,
                     sb + (uint32_t)(buf * PJ_BUF + 3 * PJ_PL) * 2,
                     wm, wn, lane);
        __syncthreads();
        if (kt + 2 < NT) stage(kt + 2, buf);
    }

    if (z != 2) {
#pragma unroll
        for (int mi = 0; mi < 4; mi++)
#pragma unroll
            for (int ni = 0; ni < 4; ni++) {
                int r = m0 + wm * 64 + mi * 16 + (lane >> 2);
                int cc = n0 + wn * 32 + ni * 8 + (lane & 3) * 2;
                float b0 = bias[cc], b1 = bias[cc + 1];
                float v0 = acc[mi][ni][0] + b0, v1 = acc[mi][ni][1] + b1;
                float v2 = acc[mi][ni][2] + b0, v3 = acc[mi][ni][3] + b1;
                __half* Ch = (z == 0) ? Qh : Kh;
                __half* Cl = (z == 0) ? Ql : Kl;
                uint32_t h, l;
                split2(v0, v1, h, l);
                *(uint32_t*)(Ch + (size_t)r * D_ + cc) = h;
                *(uint32_t*)(Cl + (size_t)r * D_ + cc) = l;
                split2(v2, v3, h, l);
                *(uint32_t*)(Ch + (size_t)(r + 8) * D_ + cc) = h;
                *(uint32_t*)(Cl + (size_t)(r + 8) * D_ + cc) = l;
            }
    } else {
        // V: stage tile [feature][token] in smem, then write transposed halves.
        float* stg = (float*)dsm;   // [128][132] floats = 67584 B
#pragma unroll
        for (int mi = 0; mi < 4; mi++)
#pragma unroll
            for (int ni = 0; ni < 4; ni++) {
                int tloc = wm * 64 + mi * 16 + (lane >> 2);
                int cloc = wn * 32 + ni * 8 + (lane & 3) * 2;
                float b0 = bias[n0 + cloc], b1 = bias[n0 + cloc + 1];
                stg[(cloc + 0) * 132 + tloc]     = acc[mi][ni][0] + b0;
                stg[(cloc + 1) * 132 + tloc]     = acc[mi][ni][1] + b1;
                stg[(cloc + 0) * 132 + tloc + 8] = acc[mi][ni][2] + b0;
                stg[(cloc + 1) * 132 + tloc + 8] = acc[mi][ni][3] + b1;
            }
        __syncthreads();
        const int fl = tid & 127, seg = tid >> 7;
        const int fg = n0 + fl;
        const int hh_ = fg >> 6, dd = fg & 63;
        const int bb = m0 >> 11;
        const int tokin = (m0 & (L_ - 1)) + seg * 64;
        __half* dh = Vth + (((size_t)(bb * H_ + hh_)) * 64 + dd) * L_ + tokin;
        __half* dl = Vtl + (((size_t)(bb * H_ + hh_)) * 64 + dd) * L_ + tokin;
#pragma unroll
        for (int i = 0; i < 64; i += 4) {
            float4 v = *(const float4*)&stg[fl * 132 + seg * 64 + i];
            uint32_t h0, l0, h1, l1;
            split2(v.x, v.y, h0, l0);
            split2(v.z, v.w, h1, l1);
            *(uint2*)(dh + i) = make_uint2(h0, h1);
            *(uint2*)(dl + i) = make_uint2(l0, l1);
        }
    }
}

// ---------------------------------------------------------------------------
// Output projection: ctx halves @ Wo + bo -> fp32 out.
// ---------------------------------------------------------------------------
__global__ __launch_bounds__(256, 2) void out_proj(
    const __half* __restrict__ Ahg, const __half* __restrict__ Alg,
    const __half* __restrict__ Bth, const __half* __restrict__ Btl,
    const float* __restrict__ bias, float* __restrict__ C32)
{
    extern __shared__ __half dsm[];
    const int tid = threadIdx.x, wid = tid >> 5, lane = tid & 31;
    const int wm = wid >> 2, wn = wid & 3;
    const int n0 = blockIdx.x * 128, m0 = blockIdx.y * 128;
    const uint32_t sb = smem_u32(dsm);

    float acc[4][4][4];
#pragma unroll
    for (int i = 0; i < 4; i++)
#pragma unroll
        for (int j = 0; j < 4; j++)
#pragma unroll
            for (int f = 0; f < 4; f++) acc[i][j][f] = 0.0f;

    const int NT = D_ / 32;

    auto stage = [&](int kt, int buf) {
        const int k0 = kt * 32;
        uint32_t ub = sb + (uint32_t)(buf * PJ_BUF) * 2;
        cp_half32(Ahg + (size_t)m0 * D_ + k0, D_, ub + 0 * PJ_PL * 2, tid, 128);
        cp_half32(Alg + (size_t)m0 * D_ + k0, D_, ub + 1 * PJ_PL * 2, tid, 128);
        cp_half32(Bth + (size_t)n0 * D_ + k0, D_, ub + 2 * PJ_PL * 2, tid, 128);
        cp_half32(Btl + (size_t)n0 * D_ + k0, D_, ub + 3 * PJ_PL * 2, tid, 128);
        CP_COMMIT();
    };

    stage(0, 0);
    stage(1, 1);

    for (int kt = 0; kt < NT; kt++) {
        if (kt + 1 < NT) { CP_WAIT1(); } else { CP_WAIT0(); }
        __syncthreads();
        const int buf = kt & 1;
        mma_block<4>(acc,
                     sb + (uint32_t)(buf * PJ_BUF + 0 * PJ_PL) * 2,
                     sb + (uint32_t)(buf * PJ_BUF + 1 * PJ_PL) * 2,
                     sb + (uint32_t)(buf * PJ_BUF + 2 * PJ_PL) * 2,
                     sb + (uint32_t)(buf * PJ_BUF + 3 * PJ_PL) * 2,
                     wm, wn, lane);
        __syncthreads();
        if (kt + 2 < NT) stage(kt + 2, buf);
    }

#pragma unroll
    for (int mi = 0; mi < 4; mi++)
#pragma unroll
        for (int ni = 0; ni < 4; ni++) {
            int r = m0 + wm * 64 + mi * 16 + (lane >> 2);
            int cc = n0 + wn * 32 + ni * 8 + (lane & 3) * 2;
            float b0 = bias[cc], b1 = bias[cc + 1];
            *(float2*)(C32 + (size_t)r * D_ + cc) =
                make_float2(acc[mi][ni][0] + b0, acc[mi][ni][1] + b1);
            *(float2*)(C32 + (size_t)(r + 8) * D_ + cc) =
                make_float2(acc[mi][ni][2] + b0, acc[mi][ni][3] + b1);
        }
}

// ---------------------------------------------------------------------------
// Scores, K-tile paired: per CTA, Q tile resident, two adjacent k-tiles.
// K1 prefetch overlaps epilogue0 stores. Emits S + per-tile partial stats.
// Dynamic smem: Qh, Ql, Kh, Kl planes (73728 B). Reduction scratch static.
// ---------------------------------------------------------------------------
#define SC_PL   (128 * STR2)
#define SC_SMEM (4 * SC_PL * 2)

__global__ __launch_bounds__(256, 2) void scores_tc(
    const float* __restrict__ rel_bias, float* __restrict__ attn,
    float2* __restrict__ pstats)
{
    extern __shared__ __half dsm[];
    __shared__ float sbias[NBIAS_];
    __shared__ float red_m[512], red_s[512];

    const int tid = threadIdx.x, wid = tid >> 5, lane = tid & 31;
    const int wm = wid >> 2, wn = wid & 3;
    const int bxp = blockIdx.x, by = blockIdx.y, bh_ = blockIdx.z;
    const int b = bh_ >> 4, h = bh_ & 15;
    const uint32_t sb = smem_u32(dsm);

    const size_t qb = (size_t)(b * L_ + by * 128) * D_ + h * HD_;

    cp_half64(g_Qh + qb, D_, sb + 0u * SC_PL * 2, tid, 128);
    cp_half64(g_Ql + qb, D_, sb + 1u * SC_PL * 2, tid, 128);
    {
        const size_t kb0 = (size_t)(b * L_ + (2 * bxp) * 128) * D_ + h * HD_;
        cp_half64(g_Kh + kb0, D_, sb + 2u * SC_PL * 2, tid, 128);
        cp_half64(g_Kl + kb0, D_, sb + 3u * SC_PL * 2, tid, 128);
    }
    CP_COMMIT();

    for (int i = tid; i < NBIAS_; i += 256) sbias[i] = rel_bias[i * H_ + h];

    CP_WAIT0();
    __syncthreads();

    const uint32_t pAh = sb + 0u * SC_PL * 2, pAl = sb + 1u * SC_PL * 2;
    const uint32_t pBh = sb + 2u * SC_PL * 2, pBl = sb + 3u * SC_PL * 2;
    float* base = attn + (size_t)bh_ * L_ * L_;

#pragma unroll
    for (int sub = 0; sub < 2; sub++) {
        const int bx = 2 * bxp + sub;

        float acc[4][4][4];
#pragma unroll
        for (int i = 0; i < 4; i++)
#pragma unroll
            for (int j = 0; j < 4; j++)
#pragma unroll
                for (int f = 0; f < 4; f++) acc[i][j][f] = 0.0f;

#pragma unroll
        for (int ks = 0; ks < 64; ks += 16) {
            uint32_t ah[4][4], al[4][4], bh[4][2], bl[4][2];
            const uint32_t aoff = (uint32_t)((wm * 64 + (lane & 15)) * STR2 + ks + (lane >> 4) * 8) * 2;
            const uint32_t boff = (uint32_t)((wn * 32 + (lane & 7)) * STR2 + ks + ((lane >> 3) & 1) * 8) * 2;
#pragma unroll
            for (int mi = 0; mi < 4; mi++) {
                ldsm4(ah[mi], pAh + aoff + mi * 16 * STR2 * 2);
                ldsm4(al[mi], pAl + aoff + mi * 16 * STR2 * 2);
            }
#pragma unroll
            for (int ni = 0; ni < 4; ni++) {
                ldsm2(bh[ni], pBh + boff + ni * 8 * STR2 * 2);
                ldsm2(bl[ni], pBl + boff + ni * 8 * STR2 * 2);
            }
#pragma unroll
            for (int mi = 0; mi < 4; mi++)
#pragma unroll
                for (int ni = 0; ni < 4; ni++) mma16816(acc[mi][ni], ah[mi], bh[ni]);
#pragma unroll
            for (int mi = 0; mi < 4; mi++)
#pragma unroll
                for (int ni = 0; ni < 4; ni++) mma16816(acc[mi][ni], ah[mi], bl[ni]);
#pragma unroll
            for (int mi = 0; mi < 4; mi++)
#pragma unroll
                for (int ni = 0; ni < 4; ni++) mma16816(acc[mi][ni], al[mi], bh[ni]);
        }

        __syncthreads();   // all K reads done before overwriting K buffer
        if (sub == 0) {
            const size_t kb1 = (size_t)(b * L_ + (2 * bxp + 1) * 128) * D_ + h * HD_;
            cp_half64(g_Kh + kb1, D_, pBh, tid, 128);
            cp_half64(g_Kl + kb1, D_, pBl, tid, 128);
            CP_COMMIT();   // overlapped with the epilogue's DRAM stores
        }

        // Epilogue: bias + store S + per-row partial stats
#pragma unroll
        for (int mi = 0; mi < 4; mi++)
#pragma unroll
            for (int rh = 0; rh < 2; rh++) {
                int rl = wm * 64 + mi * 16 + rh * 8 + (lane >> 2);
                int q = by * 128 + rl;
                float v[8];
#pragma unroll
                for (int ni = 0; ni < 4; ni++) {
                    int kc = bx * 128 + wn * 32 + ni * 8 + (lane & 3) * 2;
                    int rel0 = kc - q;     rel0 = rel0 < -128 ? -128 : (rel0 > 128 ? 128 : rel0);
                    int rel1 = kc + 1 - q; rel1 = rel1 < -128 ? -128 : (rel1 > 128 ? 128 : rel1);
                    v[ni * 2 + 0] = acc[mi][ni][rh * 2 + 0] * 0.125f + sbias[rel0 + 128];
                    v[ni * 2 + 1] = acc[mi][ni][rh * 2 + 1] * 0.125f + sbias[rel1 + 128];
                    *(float2*)(base + (size_t)q * L_ + kc) = make_float2(v[ni * 2], v[ni * 2 + 1]);
                }
                float m = v[0];
#pragma unroll
                for (int i = 1; i < 8; i++) m = fmaxf(m, v[i]);
                m = fmaxf(m, __shfl_xor_sync(0xffffffffu, m, 1));
                m = fmaxf(m, __shfl_xor_sync(0xffffffffu, m, 2));
                float s = 0.0f;
#pragma unroll
                for (int i = 0; i < 8; i++) s += __expf(v[i] - m);
                s += __shfl_xor_sync(0xffffffffu, s, 1);
                s += __shfl_xor_sync(0xffffffffu, s, 2);
                if ((lane & 3) == 0) {
                    red_m[rl * 4 + wn] = m;
                    red_s[rl * 4 + wn] = s;
                }
            }
        __syncthreads();
        if (tid < 128) {
            float m0 = red_m[tid * 4 + 0], m1 = red_m[tid * 4 + 1];
            float m2 = red_m[tid * 4 + 2], m3 = red_m[tid * 4 + 3];
            float M = fmaxf(fmaxf(m0, m1), fmaxf(m2, m3));
            float S = red_s[tid * 4 + 0] * __expf(m0 - M) + red_s[tid * 4 + 1] * __expf(m1 - M)
                    + red_s[tid * 4 + 2] * __expf(m2 - M) + red_s[tid * 4 + 3] * __expf(m3 - M);
            pstats[((size_t)bh_ * L_ + by * 128 + tid) * 16 + bx] = make_float2(M, S);
        }
        if (sub == 0) {
            CP_WAIT0();
            __syncthreads();
        }
    }
}

// ---------------------------------------------------------------------------
// Fused softmax + AV. Prologue combines 16 partial stats per row in-kernel.
// ---------------------------------------------------------------------------
#define AV_OFF_AH 36864
#define AV_OFF_AL 47104
#define AV_OFF_V  57344
#define AV_OFF_ST 77824
#define AV_SMEM   78848

__global__ __launch_bounds__(256, 2) void av_fused(
    float* __restrict__ attn, const float2* __restrict__ pstats)
{
    extern __shared__ char dsmc[];
    float*  Sbuf = (float*)dsmc;
    __half* Ahp  = (__half*)(dsmc + AV_OFF_AH);
    __half* Alp  = (__half*)(dsmc + AV_OFF_AL);
    float2* sst  = (float2*)(dsmc + AV_OFF_ST);

    const int tid = threadIdx.x, wid = tid >> 5, lane = tid & 31;
    const int wm = wid >> 2, wn = wid & 3;
    const int by = blockIdx.x, bh_ = blockIdx.y;
    const int b = bh_ >> 4, h = bh_ & 15;
    const uint32_t sb = smem_u32(dsmc);
    const uint32_t uAh = sb + AV_OFF_AH, uAl = sb + AV_OFF_AL, uV = sb + AV_OFF_V;

    const size_t pb = ((size_t)bh_ * L_ + by * 128) * L_;
    const size_t vbase = (size_t)bh_ * 64 * L_;

    if (tid < 128) {
        const float2* p = pstats + ((size_t)bh_ * L_ + by * 128 + tid) * 16;
        float2 v[16];
#pragma unroll
        for (int i = 0; i < 16; i++) v[i] = p[i];
        float M = v[0].x;
#pragma unroll
        for (int i = 1; i < 16; i++) M = fmaxf(M, v[i].x);
        float S = 0.0f;
#pragma unroll
        for (int i = 0; i < 16; i++) S += v[i].y * __expf(v[i].x - M);
        sst[tid] = make_float2(M, 1.0f / S);
    }

    float acc[4][2][4];
#pragma unroll
    for (int i = 0; i < 4; i++)
#pragma unroll
        for (int j = 0; j < 2; j++)
#pragma unroll
            for (int f = 0; f < 4; f++) acc[i][j][f] = 0.0f;

    const int NT = L_ / 32;
    const int c8 = tid & 7, r32 = tid >> 3;

    auto stage = [&](int kt, int buf) {
        const int k0 = kt * 32;
        for (int r = r32; r < 128; r += 32)
            cpa16(sb + (uint32_t)((buf * 128 + r) * SRF + c8 * 4) * 4,
                  attn + pb + (size_t)r * L_ + k0 + c8 * 4);
        cp_half32(g_Vth + vbase + k0, L_, uV + (uint32_t)buf * 10240, tid, 64);
        cp_half32(g_Vtl + vbase + k0, L_, uV + (uint32_t)buf * 10240 + 5120, tid, 64);
        CP_COMMIT();
    };

    stage(0, 0);
    stage(1, 1);

    for (int kt = 0; kt < NT; kt++) {
        if (kt + 1 < NT) { CP_WAIT1(); } else { CP_WAIT0(); }
        __syncthreads();
        const int buf = kt & 1;
        const int k0 = kt * 32;

        for (int r = r32; r < 128; r += 32) {
            float4 v = *(const float4*)(Sbuf + (buf * 128 + r) * SRF + c8 * 4);
            float2 ms = sst[r];
            float p0 = __expf(v.x - ms.x);
            float p1 = __expf(v.y - ms.x);
            float p2 = __expf(v.z - ms.x);
            float p3 = __expf(v.w - ms.x);
            *(float4*)(attn + pb + (size_t)r * L_ + k0 + c8 * 4) =
                make_float4(p0 * ms.y, p1 * ms.y, p2 * ms.y, p3 * ms.y);
            uint32_t h0, l0, h1, l1;
            split2(p0, p1, h0, l0);
            split2(p2, p3, h1, l1);
            *(uint2*)(Ahp + r * STR + c8 * 4) = make_uint2(h0, h1);
            *(uint2*)(Alp + r * STR + c8 * 4) = make_uint2(l0, l1);
        }
        __syncthreads();

        const uint32_t pBh = uV + (uint32_t)buf * 10240;
        const uint32_t pBl = pBh + 5120;
        mma_block<2>(acc, uAh, uAl, pBh, pBl, wm, wn, lane);
        __syncthreads();
        if (kt + 2 < NT) stage(kt + 2, buf);
    }

#pragma unroll
    for (int mi = 0; mi < 4; mi++)
#pragma unroll
        for (int ni = 0; ni < 2; ni++) {
            int rl = wm * 64 + mi * 16 + (lane >> 2);
            float is0 = sst[rl].y, is1 = sst[rl + 8].y;
            int tok = b * L_ + by * 128 + rl;
            int cc = h * 64 + wn * 16 + ni * 8 + (lane & 3) * 2;
            uint32_t hh, ll;
            split2(acc[mi][ni][0] * is0, acc[mi][ni][1] * is0, hh, ll);
            *(uint32_t*)(g_Ch + (size_t)tok * D_ + cc) = hh;
            *(uint32_t*)(g_Cl + (size_t)tok * D_ + cc) = ll;
            split2(acc[mi][ni][2] * is1, acc[mi][ni][3] * is1, hh, ll);
            *(uint32_t*)(g_Ch + (size_t)(tok + 8) * D_ + cc) = hh;
            *(uint32_t*)(g_Cl + (size_t)(tok + 8) * D_ + cc) = ll;
        }
}

// ---------------------------------------------------------------------------
extern "C" void kernel_launch(void* const* d_in, const int* in_sizes, int n_in,
                              void* d_out, int out_size)
{
    const float* query = (const float*)d_in[0];
    const float* key_  = (const float*)d_in[1];
    const float* value = (const float*)d_in[2];
    const float* Wq = (const float*)d_in[3];
    const float* bq = (const float*)d_in[4];
    const float* Wk = (const float*)d_in[5];
    const float* bk = (const float*)d_in[6];
    const float* Wv = (const float*)d_in[7];
    const float* bv = (const float*)d_in[8];
    const float* Wo = (const float*)d_in[9];
    const float* bo = (const float*)d_in[10];
    const float* rel_bias = (const float*)d_in[11];
    float* outp = (float*)d_out;

    static float *Ap = nullptr;
    static float2 *PSp = nullptr;
    static __half *Wth = nullptr, *Wtl = nullptr, *Vth = nullptr, *Vtl = nullptr;
    static __half *Qh = nullptr, *Ql = nullptr, *Kh = nullptr, *Kl = nullptr;
    static __half *Ch = nullptr, *Cl = nullptr, *Xh = nullptr, *Xl = nullptr;
    if (!Ap) {
        cudaGetSymbolAddress((void**)&Ap, g_attn);
        cudaGetSymbolAddress((void**)&PSp, g_pstats);
        cudaGetSymbolAddress((void**)&Wth, g_Wth);
        cudaGetSymbolAddress((void**)&Wtl, g_Wtl);
        cudaGetSymbolAddress((void**)&Vth, g_Vth);
        cudaGetSymbolAddress((void**)&Vtl, g_Vtl);
        cudaGetSymbolAddress((void**)&Qh, g_Qh);
        cudaGetSymbolAddress((void**)&Ql, g_Ql);
        cudaGetSymbolAddress((void**)&Kh, g_Kh);
        cudaGetSymbolAddress((void**)&Kl, g_Kl);
        cudaGetSymbolAddress((void**)&Ch, g_Ch);
        cudaGetSymbolAddress((void**)&Cl, g_Cl);
        cudaGetSymbolAddress((void**)&Xh, g_Xh);
        cudaGetSymbolAddress((void**)&Xl, g_Xl);
        cudaFuncSetAttribute(qkv_proj, cudaFuncAttributeMaxDynamicSharedMemorySize, PJ_SMEM);
        cudaFuncSetAttribute(out_proj, cudaFuncAttributeMaxDynamicSharedMemorySize, PJ_SMEM);
        cudaFuncSetAttribute(scores_tc, cudaFuncAttributeMaxDynamicSharedMemorySize, SC_SMEM);
        cudaFuncSetAttribute(av_fused, cudaFuncAttributeMaxDynamicSharedMemorySize, AV_SMEM);
    }

    float* attn = ((size_t)out_size >= OUT_ELEMS + ATT_ELEMS) ? (outp + OUT_ELEMS) : Ap;
    const size_t WSZ = (size_t)D_ * D_;

    dim3 bT(32, 8);
    wsplit4<<<dim3(D_ / 32, D_ / 32, 4), bT>>>(Wq, Wk, Wv, Wo, Wth, Wtl);
    xsplit<<<dim3((unsigned)((size_t)BL_ * D_ / (256 * 8)), 3), 256>>>(query, key_, value, Xh, Xl);

    dim3 gQKV(D_ / 128, BL_ / 128, 3);   // (8, 32, 3)
    qkv_proj<<<gQKV, 256, PJ_SMEM>>>(Xh, Xl, Wth, Wtl,
                                     bq, bk, bv, Qh, Ql, Kh, Kl, Vth, Vtl);

    dim3 gScores(L_ / 256, L_ / 128, B_ * H_);  // (8, 16, 32) — paired k-tiles
    scores_tc<<<gScores, 256, SC_SMEM>>>(rel_bias, attn, PSp);

    dim3 gAV(L_ / 128, B_ * H_);       // (16, 32)
    av_fused<<<gAV, 256, AV_SMEM>>>(attn, PSp);

    out_proj<<<dim3(D_ / 128, BL_ / 128), 256, PJ_SMEM>>>(Ch, Cl, Wth + 3 * WSZ, Wtl + 3 * WSZ,
                                                          bo, outp);
}

// round 17
// speedup vs baseline: 1.1941x; 1.0125x over previous
#include <cuda_runtime.h>
#include <cuda_fp16.h>
#include <cstdint>
#include <cstddef>

#define B_   2
#define L_   2048
#define D_   1024
#define H_   16
#define HD_  64
#define BL_  (B_ * L_)
#define NBIAS_ 257
#define STR  40   // smem row stride (halfs) for 32-wide half tiles
#define STR2 72   // smem row stride (halfs) for 64-wide half tiles
#define SRF  36   // smem row stride (floats) for 32-wide fp32 tiles

static const size_t OUT_ELEMS = (size_t)BL_ * D_;
static const size_t ATT_ELEMS = (size_t)B_ * H_ * L_ * (size_t)L_;

// Device-global scratch (allocation-free rule)
__device__ __half g_Xh[3ull * BL_ * D_], g_Xl[3ull * BL_ * D_];  // split inputs q,k,v
__device__ __half g_Qh[(size_t)BL_ * D_], g_Ql[(size_t)BL_ * D_];
__device__ __half g_Kh[(size_t)BL_ * D_], g_Kl[(size_t)BL_ * D_];
__device__ __half g_Ch[(size_t)BL_ * D_], g_Cl[(size_t)BL_ * D_];
__device__ __half g_Wth[4ull * D_ * D_];
__device__ __half g_Wtl[4ull * D_ * D_];
__device__ __half g_Vth[(size_t)BL_ * D_]; // V transposed: [(b*16+h)*64+d][tok]
__device__ __half g_Vtl[(size_t)BL_ * D_];
__device__ float2 g_pstats[(size_t)B_ * H_ * L_ * 16];  // per (row, ktile) partial (m, s)
__device__ float  g_attn[(size_t)B_ * H_ * L_ * (size_t)L_]; // fallback

// ---------------------------------------------------------------------------
// Helpers
// ---------------------------------------------------------------------------
__device__ __forceinline__ uint32_t smem_u32(const void* p) {
    uint32_t a;
    asm("{ .reg .u64 t; cvta.to.shared.u64 t, %1; cvt.u32.u64 %0, t; }" : "=r"(a) : "l"(p));
    return a;
}
__device__ __forceinline__ void cpa16(uint32_t d, const void* s) {
    asm volatile("cp.async.cg.shared.global [%0], [%1], 16;" :: "r"(d), "l"(s));
}
#define CP_COMMIT() asm volatile("cp.async.commit_group;" ::: "memory")
#define CP_WAIT0()  asm volatile("cp.async.wait_group 0;" ::: "memory")
#define CP_WAIT1()  asm volatile("cp.async.wait_group 1;" ::: "memory")

__device__ __forceinline__ void ldsm4(uint32_t r[4], uint32_t addr) {
    asm volatile("ldmatrix.sync.aligned.m8n8.x4.shared.b16 {%0,%1,%2,%3}, [%4];"
                 : "=r"(r[0]), "=r"(r[1]), "=r"(r[2]), "=r"(r[3]) : "r"(addr));
}
__device__ __forceinline__ void ldsm2(uint32_t r[2], uint32_t addr) {
    asm volatile("ldmatrix.sync.aligned.m8n8.x2.shared.b16 {%0,%1}, [%2];"
                 : "=r"(r[0]), "=r"(r[1]) : "r"(addr));
}
__device__ __forceinline__ void mma16816(float c[4], const uint32_t a[4], const uint32_t b[2]) {
    asm volatile("mma.sync.aligned.m16n8k16.row.col.f32.f16.f16.f32 "
                 "{%0,%1,%2,%3}, {%4,%5,%6,%7}, {%8,%9}, {%0,%1,%2,%3};"
                 : "+f"(c[0]), "+f"(c[1]), "+f"(c[2]), "+f"(c[3])
                 : "r"(a[0]), "r"(a[1]), "r"(a[2]), "r"(a[3]), "r"(b[0]), "r"(b[1]));
}

__device__ __forceinline__ uint32_t h2u(__half2 v) { return *reinterpret_cast<uint32_t*>(&v); }

__device__ __forceinline__ void split2(float x, float y, uint32_t& hi, uint32_t& lo) {
    __half h0 = __float2half_rn(x), h1 = __float2half_rn(y);
    __half l0 = __float2half_rn(x - __half2float(h0));
    __half l1 = __float2half_rn(y - __half2float(h1));
    hi = h2u(__halves2half2(h0, h1));
    lo = h2u(__halves2half2(l0, l1));
}

// Async copy of half tile [rows][32] (gs = global row stride, halfs)
__device__ __forceinline__ void cp_half32(const __half* __restrict__ g, int gs,
                                          uint32_t sm, int tid, int rows) {
    int c = tid & 3, r0 = tid >> 2;
    for (int r = r0; r < rows; r += 64)
        cpa16(sm + (uint32_t)(r * STR + c * 8) * 2, g + (size_t)r * gs + c * 8);
}
// Async copy of half tile [rows][64], stride STR2
__device__ __forceinline__ void cp_half64(const __half* __restrict__ g, int gs,
                                          uint32_t sm, int tid, int rows) {
    int c = tid & 7, r0 = tid >> 3;
    for (int r = r0; r < rows; r += 32)
        cpa16(sm + (uint32_t)(r * STR2 + c * 8) * 2, g + (size_t)r * gs + c * 8);
}

// ---------------------------------------------------------------------------
// Prep kernels
// ---------------------------------------------------------------------------
__global__ __launch_bounds__(256) void xsplit(
    const float* __restrict__ X0, const float* __restrict__ X1,
    const float* __restrict__ X2, __half* __restrict__ Xh, __half* __restrict__ Xl)
{
    const float* Xs[3] = {X0, X1, X2};
    const float* X = Xs[blockIdx.y];
    __half* xh = Xh + (size_t)blockIdx.y * BL_ * D_;
    __half* xl = Xl + (size_t)blockIdx.y * BL_ * D_;
    size_t i = ((size_t)blockIdx.x * 256 + threadIdx.x) * 8;
    float4 a = *(const float4*)(X + i);
    float4 b = *(const float4*)(X + i + 4);
    uint32_t h0, l0, h1, l1, h2, l2, h3, l3;
    split2(a.x, a.y, h0, l0);
    split2(a.z, a.w, h1, l1);
    split2(b.x, b.y, h2, l2);
    split2(b.z, b.w, h3, l3);
    *(uint4*)(xh + i) = make_uint4(h0, h1, h2, h3);
    *(uint4*)(xl + i) = make_uint4(l0, l1, l2, l3);
}

__global__ void wsplit4(const float* __restrict__ W0, const float* __restrict__ W1,
                        const float* __restrict__ W2, const float* __restrict__ W3,
                        __half* __restrict__ Th, __half* __restrict__ Tl) {
    __shared__ float t[32][33];
    const float* Ws[4] = {W0, W1, W2, W3};
    const float* W = Ws[blockIdx.z];
    __half* th = Th + (size_t)blockIdx.z * D_ * D_;
    __half* tl = Tl + (size_t)blockIdx.z * D_ * D_;
    int bx = blockIdx.x * 32, by = blockIdx.y * 32;
    int tx = threadIdx.x, ty = threadIdx.y;
    for (int i = ty; i < 32; i += 8)
        t[i][tx] = W[(size_t)(by + i) * D_ + bx + tx];
    __syncthreads();
    for (int i = ty; i < 32; i += 8) {
        float v = t[tx][i];
        __half h = __float2half_rn(v);
        th[(size_t)(bx + i) * D_ + by + tx] = h;
        tl[(size_t)(bx + i) * D_ + by + tx] = __float2half_rn(v - __half2float(h));
    }
}

// ---------------------------------------------------------------------------
// Shared MMA block helper (term-major issue order), A/B stride STR
// ---------------------------------------------------------------------------
#define PJ_PL   (128 * STR)
#define PJ_BUF  (4 * PJ_PL)
#define PJ_SMEM (2 * PJ_BUF * 2)

template <int NI>
__device__ __forceinline__ void mma_block(
    float acc[4][NI][4], const uint32_t pAh, const uint32_t pAl,
    const uint32_t pBh, const uint32_t pBl,
    int wm, int wn, int lane)
{
#pragma unroll
    for (int ks = 0; ks < 32; ks += 16) {
        uint32_t ah[4][4], al[4][4], bh[NI][2], bl[NI][2];
        const uint32_t aoff = (uint32_t)((wm * 64 + (lane & 15)) * STR + ks + (lane >> 4) * 8) * 2;
        const uint32_t boff = (uint32_t)((wn * (8 * NI) + (lane & 7)) * STR + ks + ((lane >> 3) & 1) * 8) * 2;
#pragma unroll
        for (int mi = 0; mi < 4; mi++) {
            ldsm4(ah[mi], pAh + aoff + mi * 16 * STR * 2);
            ldsm4(al[mi], pAl + aoff + mi * 16 * STR * 2);
        }
#pragma unroll
        for (int ni = 0; ni < NI; ni++) {
            ldsm2(bh[ni], pBh + boff + ni * 8 * STR * 2);
            ldsm2(bl[ni], pBl + boff + ni * 8 * STR * 2);
        }
#pragma unroll
        for (int mi = 0; mi < 4; mi++)
#pragma unroll
            for (int ni = 0; ni < NI; ni++) mma16816(acc[mi][ni], ah[mi], bh[ni]);
#pragma unroll
        for (int mi = 0; mi < 4; mi++)
#pragma unroll
            for (int ni = 0; ni < NI; ni++) mma16816(acc[mi][ni], ah[mi], bl[ni]);
#pragma unroll
        for (int mi = 0; mi < 4; mi++)
#pragma unroll
            for (int ni = 0; ni < NI; ni++) mma16816(acc[mi][ni], al[mi], bh[ni]);
    }
}

// ---------------------------------------------------------------------------
// Merged Q/K/V projection: grid (8, 32, 3). z==2 (V) writes transposed split
// halves directly via a smem-staged transpose.
// ---------------------------------------------------------------------------
__global__ __launch_bounds__(256, 2) void qkv_proj(
    const __half* __restrict__ Xh, const __half* __restrict__ Xl,
    const __half* __restrict__ Wth, const __half* __restrict__ Wtl,
    const float* __restrict__ bq, const float* __restrict__ bk,
    const float* __restrict__ bv,
    __half* __restrict__ Qh, __half* __restrict__ Ql,
    __half* __restrict__ Kh, __half* __restrict__ Kl,
    __half* __restrict__ Vth, __half* __restrict__ Vtl)
{
    extern __shared__ __half dsm[];
    const int tid = threadIdx.x, wid = tid >> 5, lane = tid & 31;
    const int wm = wid >> 2, wn = wid & 3;
    const int n0 = blockIdx.x * 128, m0 = blockIdx.y * 128;
    const int z = blockIdx.z;
    const uint32_t sb = smem_u32(dsm);

    const __half* Ahg = Xh + (size_t)z * BL_ * D_;
    const __half* Alg = Xl + (size_t)z * BL_ * D_;
    const __half* Bth = Wth + (size_t)z * D_ * D_;
    const __half* Btl = Wtl + (size_t)z * D_ * D_;
    const float* bias = (z == 0) ? bq : (z == 1) ? bk : bv;

    float acc[4][4][4];
#pragma unroll
    for (int i = 0; i < 4; i++)
#pragma unroll
        for (int j = 0; j < 4; j++)
#pragma unroll
            for (int f = 0; f < 4; f++) acc[i][j][f] = 0.0f;

    const int NT = D_ / 32;

    auto stage = [&](int kt, int buf) {
        const int k0 = kt * 32;
        uint32_t ub = sb + (uint32_t)(buf * PJ_BUF) * 2;
        cp_half32(Ahg + (size_t)m0 * D_ + k0, D_, ub + 0 * PJ_PL * 2, tid, 128);
        cp_half32(Alg + (size_t)m0 * D_ + k0, D_, ub + 1 * PJ_PL * 2, tid, 128);
        cp_half32(Bth + (size_t)n0 * D_ + k0, D_, ub + 2 * PJ_PL * 2, tid, 128);
        cp_half32(Btl + (size_t)n0 * D_ + k0, D_, ub + 3 * PJ_PL * 2, tid, 128);
        CP_COMMIT();
    };

    stage(0, 0);
    stage(1, 1);

    for (int kt = 0; kt < NT; kt++) {
        if (kt + 1 < NT) { CP_WAIT1(); } else { CP_WAIT0(); }
        __syncthreads();
        const int buf = kt & 1;
        mma_block<4>(acc,
                     sb + (uint32_t)(buf * PJ_BUF + 0 * PJ_PL) * 2,
                     sb + (uint32_t)(buf * PJ_BUF + 1 * PJ_PL) * 2,
                     sb + (uint32_t)(buf * PJ_BUF + 2 * PJ_PL) * 2,
                     sb + (uint32_t)(buf * PJ_BUF + 3 * PJ_PL) * 2,
                     wm, wn, lane);
        __syncthreads();
        if (kt + 2 < NT) stage(kt + 2, buf);
    }

    if (z != 2) {
#pragma unroll
        for (int mi = 0; mi < 4; mi++)
#pragma unroll
            for (int ni = 0; ni < 4; ni++) {
                int r = m0 + wm * 64 + mi * 16 + (lane >> 2);
                int cc = n0 + wn * 32 + ni * 8 + (lane & 3) * 2;
                float b0 = bias[cc], b1 = bias[cc + 1];
                float v0 = acc[mi][ni][0] + b0, v1 = acc[mi][ni][1] + b1;
                float v2 = acc[mi][ni][2] + b0, v3 = acc[mi][ni][3] + b1;
                __half* Ch = (z == 0) ? Qh : Kh;
                __half* Cl = (z == 0) ? Ql : Kl;
                uint32_t h, l;
                split2(v0, v1, h, l);
                *(uint32_t*)(Ch + (size_t)r * D_ + cc) = h;
                *(uint32_t*)(Cl + (size_t)r * D_ + cc) = l;
                split2(v2, v3, h, l);
                *(uint32_t*)(Ch + (size_t)(r + 8) * D_ + cc) = h;
                *(uint32_t*)(Cl + (size_t)(r + 8) * D_ + cc) = l;
            }
    } else {
        // V: stage tile [feature][token] in smem, then write transposed halves.
        float* stg = (float*)dsm;   // [128][132] floats = 67584 B
#pragma unroll
        for (int mi = 0; mi < 4; mi++)
#pragma unroll
            for (int ni = 0; ni < 4; ni++) {
                int tloc = wm * 64 + mi * 16 + (lane >> 2);
                int cloc = wn * 32 + ni * 8 + (lane & 3) * 2;
                float b0 = bias[n0 + cloc], b1 = bias[n0 + cloc + 1];
                stg[(cloc + 0) * 132 + tloc]     = acc[mi][ni][0] + b0;
                stg[(cloc + 1) * 132 + tloc]     = acc[mi][ni][1] + b1;
                stg[(cloc + 0) * 132 + tloc + 8] = acc[mi][ni][2] + b0;
                stg[(cloc + 1) * 132 + tloc + 8] = acc[mi][ni][3] + b1;
            }
        __syncthreads();
        const int fl = tid & 127, seg = tid >> 7;
        const int fg = n0 + fl;
        const int hh_ = fg >> 6, dd = fg & 63;
        const int bb = m0 >> 11;
        const int tokin = (m0 & (L_ - 1)) + seg * 64;
        __half* dh = Vth + (((size_t)(bb * H_ + hh_)) * 64 + dd) * L_ + tokin;
        __half* dl = Vtl + (((size_t)(bb * H_ + hh_)) * 64 + dd) * L_ + tokin;
#pragma unroll
        for (int i = 0; i < 64; i += 4) {
            float4 v = *(const float4*)&stg[fl * 132 + seg * 64 + i];
            uint32_t h0, l0, h1, l1;
            split2(v.x, v.y, h0, l0);
            split2(v.z, v.w, h1, l1);
            *(uint2*)(dh + i) = make_uint2(h0, h1);
            *(uint2*)(dl + i) = make_uint2(l0, l1);
        }
    }
}

// ---------------------------------------------------------------------------
// Output projection: ctx halves @ Wo + bo -> fp32 out.
// ---------------------------------------------------------------------------
__global__ __launch_bounds__(256, 2) void out_proj(
    const __half* __restrict__ Ahg, const __half* __restrict__ Alg,
    const __half* __restrict__ Bth, const __half* __restrict__ Btl,
    const float* __restrict__ bias, float* __restrict__ C32)
{
    extern __shared__ __half dsm[];
    const int tid = threadIdx.x, wid = tid >> 5, lane = tid & 31;
    const int wm = wid >> 2, wn = wid & 3;
    const int n0 = blockIdx.x * 128, m0 = blockIdx.y * 128;
    const uint32_t sb = smem_u32(dsm);

    float acc[4][4][4];
#pragma unroll
    for (int i = 0; i < 4; i++)
#pragma unroll
        for (int j = 0; j < 4; j++)
#pragma unroll
            for (int f = 0; f < 4; f++) acc[i][j][f] = 0.0f;

    const int NT = D_ / 32;

    auto stage = [&](int kt, int buf) {
        const int k0 = kt * 32;
        uint32_t ub = sb + (uint32_t)(buf * PJ_BUF) * 2;
        cp_half32(Ahg + (size_t)m0 * D_ + k0, D_, ub + 0 * PJ_PL * 2, tid, 128);
        cp_half32(Alg + (size_t)m0 * D_ + k0, D_, ub + 1 * PJ_PL * 2, tid, 128);
        cp_half32(Bth + (size_t)n0 * D_ + k0, D_, ub + 2 * PJ_PL * 2, tid, 128);
        cp_half32(Btl + (size_t)n0 * D_ + k0, D_, ub + 3 * PJ_PL * 2, tid, 128);
        CP_COMMIT();
    };

    stage(0, 0);
    stage(1, 1);

    for (int kt = 0; kt < NT; kt++) {
        if (kt + 1 < NT) { CP_WAIT1(); } else { CP_WAIT0(); }
        __syncthreads();
        const int buf = kt & 1;
        mma_block<4>(acc,
                     sb + (uint32_t)(buf * PJ_BUF + 0 * PJ_PL) * 2,
                     sb + (uint32_t)(buf * PJ_BUF + 1 * PJ_PL) * 2,
                     sb + (uint32_t)(buf * PJ_BUF + 2 * PJ_PL) * 2,
                     sb + (uint32_t)(buf * PJ_BUF + 3 * PJ_PL) * 2,
                     wm, wn, lane);
        __syncthreads();
        if (kt + 2 < NT) stage(kt + 2, buf);
    }

#pragma unroll
    for (int mi = 0; mi < 4; mi++)
#pragma unroll
        for (int ni = 0; ni < 4; ni++) {
            int r = m0 + wm * 64 + mi * 16 + (lane >> 2);
            int cc = n0 + wn * 32 + ni * 8 + (lane & 3) * 2;
            float b0 = bias[cc], b1 = bias[cc + 1];
            *(float2*)(C32 + (size_t)r * D_ + cc) =
                make_float2(acc[mi][ni][0] + b0, acc[mi][ni][1] + b1);
            *(float2*)(C32 + (size_t)(r + 8) * D_ + cc) =
                make_float2(acc[mi][ni][2] + b0, acc[mi][ni][3] + b1);
        }
}

// ---------------------------------------------------------------------------
// Scores, 4-way K-tile paired: Q tile resident across four adjacent k-tiles.
// Next-K prefetch overlaps each epilogue's S stores.
// ---------------------------------------------------------------------------
#define SC_PL   (128 * STR2)
#define SC_SMEM (4 * SC_PL * 2)

__global__ __launch_bounds__(256, 2) void scores_tc(
    const float* __restrict__ rel_bias, float* __restrict__ attn,
    float2* __restrict__ pstats)
{
    extern __shared__ __half dsm[];
    __shared__ float sbias[NBIAS_];
    __shared__ float red_m[512], red_s[512];

    const int tid = threadIdx.x, wid = tid >> 5, lane = tid & 31;
    const int wm = wid >> 2, wn = wid & 3;
    const int bxp = blockIdx.x, by = blockIdx.y, bh_ = blockIdx.z;
    const int b = bh_ >> 4, h = bh_ & 15;
    const uint32_t sb = smem_u32(dsm);

    const size_t qb = (size_t)(b * L_ + by * 128) * D_ + h * HD_;

    cp_half64(g_Qh + qb, D_, sb + 0u * SC_PL * 2, tid, 128);
    cp_half64(g_Ql + qb, D_, sb + 1u * SC_PL * 2, tid, 128);
    {
        const size_t kb0 = (size_t)(b * L_ + (4 * bxp) * 128) * D_ + h * HD_;
        cp_half64(g_Kh + kb0, D_, sb + 2u * SC_PL * 2, tid, 128);
        cp_half64(g_Kl + kb0, D_, sb + 3u * SC_PL * 2, tid, 128);
    }
    CP_COMMIT();

    for (int i = tid; i < NBIAS_; i += 256) sbias[i] = rel_bias[i * H_ + h];

    CP_WAIT0();
    __syncthreads();

    const uint32_t pAh = sb + 0u * SC_PL * 2, pAl = sb + 1u * SC_PL * 2;
    const uint32_t pBh = sb + 2u * SC_PL * 2, pBl = sb + 3u * SC_PL * 2;
    float* base = attn + (size_t)bh_ * L_ * L_;

#pragma unroll 1
    for (int sub = 0; sub < 4; sub++) {
        const int bx = 4 * bxp + sub;

        float acc[4][4][4];
#pragma unroll
        for (int i = 0; i < 4; i++)
#pragma unroll
            for (int j = 0; j < 4; j++)
#pragma unroll
                for (int f = 0; f < 4; f++) acc[i][j][f] = 0.0f;

#pragma unroll
        for (int ks = 0; ks < 64; ks += 16) {
            uint32_t ah[4][4], al[4][4], bh[4][2], bl[4][2];
            const uint32_t aoff = (uint32_t)((wm * 64 + (lane & 15)) * STR2 + ks + (lane >> 4) * 8) * 2;
            const uint32_t boff = (uint32_t)((wn * 32 + (lane & 7)) * STR2 + ks + ((lane >> 3) & 1) * 8) * 2;
#pragma unroll
            for (int mi = 0; mi < 4; mi++) {
                ldsm4(ah[mi], pAh + aoff + mi * 16 * STR2 * 2);
                ldsm4(al[mi], pAl + aoff + mi * 16 * STR2 * 2);
            }
#pragma unroll
            for (int ni = 0; ni < 4; ni++) {
                ldsm2(bh[ni], pBh + boff + ni * 8 * STR2 * 2);
                ldsm2(bl[ni], pBl + boff + ni * 8 * STR2 * 2);
            }
#pragma unroll
            for (int mi = 0; mi < 4; mi++)
#pragma unroll
                for (int ni = 0; ni < 4; ni++) mma16816(acc[mi][ni], ah[mi], bh[ni]);
#pragma unroll
            for (int mi = 0; mi < 4; mi++)
#pragma unroll
                for (int ni = 0; ni < 4; ni++) mma16816(acc[mi][ni], ah[mi], bl[ni]);
#pragma unroll
            for (int mi = 0; mi < 4; mi++)
#pragma unroll
                for (int ni = 0; ni < 4; ni++) mma16816(acc[mi][ni], al[mi], bh[ni]);
        }

        __syncthreads();   // all K reads done before overwriting K buffer
        if (sub < 3) {
            const size_t kbn = (size_t)(b * L_ + (4 * bxp + sub + 1) * 128) * D_ + h * HD_;
            cp_half64(g_Kh + kbn, D_, pBh, tid, 128);
            cp_half64(g_Kl + kbn, D_, pBl, tid, 128);
            CP_COMMIT();   // overlapped with the epilogue's DRAM stores
        }

        // Epilogue: bias + store S + per-row partial stats
#pragma unroll
        for (int mi = 0; mi < 4; mi++)
#pragma unroll
            for (int rh = 0; rh < 2; rh++) {
                int rl = wm * 64 + mi * 16 + rh * 8 + (lane >> 2);
                int q = by * 128 + rl;
                float v[8];
#pragma unroll
                for (int ni = 0; ni < 4; ni++) {
                    int kc = bx * 128 + wn * 32 + ni * 8 + (lane & 3) * 2;
                    int rel0 = kc - q;     rel0 = rel0 < -128 ? -128 : (rel0 > 128 ? 128 : rel0);
                    int rel1 = kc + 1 - q; rel1 = rel1 < -128 ? -128 : (rel1 > 128 ? 128 : rel1);
                    v[ni * 2 + 0] = acc[mi][ni][rh * 2 + 0] * 0.125f + sbias[rel0 + 128];
                    v[ni * 2 + 1] = acc[mi][ni][rh * 2 + 1] * 0.125f + sbias[rel1 + 128];
                    *(float2*)(base + (size_t)q * L_ + kc) = make_float2(v[ni * 2], v[ni * 2 + 1]);
                }
                float m = v[0];
#pragma unroll
                for (int i = 1; i < 8; i++) m = fmaxf(m, v[i]);
                m = fmaxf(m, __shfl_xor_sync(0xffffffffu, m, 1));
                m = fmaxf(m, __shfl_xor_sync(0xffffffffu, m, 2));
                float s = 0.0f;
#pragma unroll
                for (int i = 0; i < 8; i++) s += __expf(v[i] - m);
                s += __shfl_xor_sync(0xffffffffu, s, 1);
                s += __shfl_xor_sync(0xffffffffu, s, 2);
                if ((lane & 3) == 0) {
                    red_m[rl * 4 + wn] = m;
                    red_s[rl * 4 + wn] = s;
                }
            }
        __syncthreads();
        if (tid < 128) {
            float m0 = red_m[tid * 4 + 0], m1 = red_m[tid * 4 + 1];
            float m2 = red_m[tid * 4 + 2], m3 = red_m[tid * 4 + 3];
            float M = fmaxf(fmaxf(m0, m1), fmaxf(m2, m3));
            float S = red_s[tid * 4 + 0] * __expf(m0 - M) + red_s[tid * 4 + 1] * __expf(m1 - M)
                    + red_s[tid * 4 + 2] * __expf(m2 - M) + red_s[tid * 4 + 3] * __expf(m3 - M);
            pstats[((size_t)bh_ * L_ + by * 128 + tid) * 16 + bx] = make_float2(M, S);
        }
        if (sub < 3) {
            CP_WAIT0();
            __syncthreads();
        }
    }
}

// ---------------------------------------------------------------------------
// Fused softmax + AV. Prologue combines 16 partial stats per row in-kernel.
// ---------------------------------------------------------------------------
#define AV_OFF_AH 36864
#define AV_OFF_AL 47104
#define AV_OFF_V  57344
#define AV_OFF_ST 77824
#define AV_SMEM   78848

__global__ __launch_bounds__(256, 2) void av_fused(
    float* __restrict__ attn, const float2* __restrict__ pstats)
{
    extern __shared__ char dsmc[];
    float*  Sbuf = (float*)dsmc;
    __half* Ahp  = (__half*)(dsmc + AV_OFF_AH);
    __half* Alp  = (__half*)(dsmc + AV_OFF_AL);
    float2* sst  = (float2*)(dsmc + AV_OFF_ST);

    const int tid = threadIdx.x, wid = tid >> 5, lane = tid & 31;
    const int wm = wid >> 2, wn = wid & 3;
    const int by = blockIdx.x, bh_ = blockIdx.y;
    const int b = bh_ >> 4, h = bh_ & 15;
    const uint32_t sb = smem_u32(dsmc);
    const uint32_t uAh = sb + AV_OFF_AH, uAl = sb + AV_OFF_AL, uV = sb + AV_OFF_V;

    const size_t pb = ((size_t)bh_ * L_ + by * 128) * L_;
    const size_t vbase = (size_t)bh_ * 64 * L_;

    if (tid < 128) {
        const float2* p = pstats + ((size_t)bh_ * L_ + by * 128 + tid) * 16;
        float2 v[16];
#pragma unroll
        for (int i = 0; i < 16; i++) v[i] = p[i];
        float M = v[0].x;
#pragma unroll
        for (int i = 1; i < 16; i++) M = fmaxf(M, v[i].x);
        float S = 0.0f;
#pragma unroll
        for (int i = 0; i < 16; i++) S += v[i].y * __expf(v[i].x - M);
        sst[tid] = make_float2(M, 1.0f / S);
    }

    float acc[4][2][4];
#pragma unroll
    for (int i = 0; i < 4; i++)
#pragma unroll
        for (int j = 0; j < 2; j++)
#pragma unroll
            for (int f = 0; f < 4; f++) acc[i][j][f] = 0.0f;

    const int NT = L_ / 32;
    const int c8 = tid & 7, r32 = tid >> 3;

    auto stage = [&](int kt, int buf) {
        const int k0 = kt * 32;
        for (int r = r32; r < 128; r += 32)
            cpa16(sb + (uint32_t)((buf * 128 + r) * SRF + c8 * 4) * 4,
                  attn + pb + (size_t)r * L_ + k0 + c8 * 4);
        cp_half32(g_Vth + vbase + k0, L_, uV + (uint32_t)buf * 10240, tid, 64);
        cp_half32(g_Vtl + vbase + k0, L_, uV + (uint32_t)buf * 10240 + 5120, tid, 64);
        CP_COMMIT();
    };

    stage(0, 0);
    stage(1, 1);

    for (int kt = 0; kt < NT; kt++) {
        if (kt + 1 < NT) { CP_WAIT1(); } else { CP_WAIT0(); }
        __syncthreads();
        const int buf = kt & 1;
        const int k0 = kt * 32;

        for (int r = r32; r < 128; r += 32) {
            float4 v = *(const float4*)(Sbuf + (buf * 128 + r) * SRF + c8 * 4);
            float2 ms = sst[r];
            float p0 = __expf(v.x - ms.x);
            float p1 = __expf(v.y - ms.x);
            float p2 = __expf(v.z - ms.x);
            float p3 = __expf(v.w - ms.x);
            *(float4*)(attn + pb + (size_t)r * L_ + k0 + c8 * 4) =
                make_float4(p0 * ms.y, p1 * ms.y, p2 * ms.y, p3 * ms.y);
            uint32_t h0, l0, h1, l1;
            split2(p0, p1, h0, l0);
            split2(p2, p3, h1, l1);
            *(uint2*)(Ahp + r * STR + c8 * 4) = make_uint2(h0, h1);
            *(uint2*)(Alp + r * STR + c8 * 4) = make_uint2(l0, l1);
        }
        __syncthreads();

        const uint32_t pBh = uV + (uint32_t)buf * 10240;
        const uint32_t pBl = pBh + 5120;
        mma_block<2>(acc, uAh, uAl, pBh, pBl, wm, wn, lane);
        __syncthreads();
        if (kt + 2 < NT) stage(kt + 2, buf);
    }

#pragma unroll
    for (int mi = 0; mi < 4; mi++)
#pragma unroll
        for (int ni = 0; ni < 2; ni++) {
            int rl = wm * 64 + mi * 16 + (lane >> 2);
            float is0 = sst[rl].y, is1 = sst[rl + 8].y;
            int tok = b * L_ + by * 128 + rl;
            int cc = h * 64 + wn * 16 + ni * 8 + (lane & 3) * 2;
            uint32_t hh, ll;
            split2(acc[mi][ni][0] * is0, acc[mi][ni][1] * is0, hh, ll);
            *(uint32_t*)(g_Ch + (size_t)tok * D_ + cc) = hh;
            *(uint32_t*)(g_Cl + (size_t)tok * D_ + cc) = ll;
            split2(acc[mi][ni][2] * is1, acc[mi][ni][3] * is1, hh, ll);
            *(uint32_t*)(g_Ch + (size_t)(tok + 8) * D_ + cc) = hh;
            *(uint32_t*)(g_Cl + (size_t)(tok + 8) * D_ + cc) = ll;
        }
}

// ---------------------------------------------------------------------------
extern "C" void kernel_launch(void* const* d_in, const int* in_sizes, int n_in,
                              void* d_out, int out_size)
{
    const float* query = (const float*)d_in[0];
    const float* key_  = (const float*)d_in[1];
    const float* value = (const float*)d_in[2];
    const float* Wq = (const float*)d_in[3];
    const float* bq = (const float*)d_in[4];
    const float* Wk = (const float*)d_in[5];
    const float* bk = (const float*)d_in[6];
    const float* Wv = (const float*)d_in[7];
    const float* bv = (const float*)d_in[8];
    const float* Wo = (const float*)d_in[9];
    const float* bo = (const float*)d_in[10];
    const float* rel_bias = (const float*)d_in[11];
    float* outp = (float*)d_out;

    static float *Ap = nullptr;
    static float2 *PSp = nullptr;
    static __half *Wth = nullptr, *Wtl = nullptr, *Vth = nullptr, *Vtl = nullptr;
    static __half *Qh = nullptr, *Ql = nullptr, *Kh = nullptr, *Kl = nullptr;
    static __half *Ch = nullptr, *Cl = nullptr, *Xh = nullptr, *Xl = nullptr;
    if (!Ap) {
        cudaGetSymbolAddress((void**)&Ap, g_attn);
        cudaGetSymbolAddress((void**)&PSp, g_pstats);
        cudaGetSymbolAddress((void**)&Wth, g_Wth);
        cudaGetSymbolAddress((void**)&Wtl, g_Wtl);
        cudaGetSymbolAddress((void**)&Vth, g_Vth);
        cudaGetSymbolAddress((void**)&Vtl, g_Vtl);
        cudaGetSymbolAddress((void**)&Qh, g_Qh);
        cudaGetSymbolAddress((void**)&Ql, g_Ql);
        cudaGetSymbolAddress((void**)&Kh, g_Kh);
        cudaGetSymbolAddress((void**)&Kl, g_Kl);
        cudaGetSymbolAddress((void**)&Ch, g_Ch);
        cudaGetSymbolAddress((void**)&Cl, g_Cl);
        cudaGetSymbolAddress((void**)&Xh, g_Xh);
        cudaGetSymbolAddress((void**)&Xl, g_Xl);
        cudaFuncSetAttribute(qkv_proj, cudaFuncAttributeMaxDynamicSharedMemorySize, PJ_SMEM);
        cudaFuncSetAttribute(out_proj, cudaFuncAttributeMaxDynamicSharedMemorySize, PJ_SMEM);
        cudaFuncSetAttribute(scores_tc, cudaFuncAttributeMaxDynamicSharedMemorySize, SC_SMEM);
        cudaFuncSetAttribute(av_fused, cudaFuncAttributeMaxDynamicSharedMemorySize, AV_SMEM);
    }

    float* attn = ((size_t)out_size >= OUT_ELEMS + ATT_ELEMS) ? (outp + OUT_ELEMS) : Ap;
    const size_t WSZ = (size_t)D_ * D_;

    dim3 bT(32, 8);
    wsplit4<<<dim3(D_ / 32, D_ / 32, 4), bT>>>(Wq, Wk, Wv, Wo, Wth, Wtl);
    xsplit<<<dim3((unsigned)((size_t)BL_ * D_ / (256 * 8)), 3), 256>>>(query, key_, value, Xh, Xl);

    dim3 gQKV(D_ / 128, BL_ / 128, 3);   // (8, 32, 3)
    qkv_proj<<<gQKV, 256, PJ_SMEM>>>(Xh, Xl, Wth, Wtl,
                                     bq, bk, bv, Qh, Ql, Kh, Kl, Vth, Vtl);

    dim3 gScores(L_ / 512, L_ / 128, B_ * H_);  // (4, 16, 32) — 4-way paired k-tiles
    scores_tc<<<gScores, 256, SC_SMEM>>>(rel_bias, attn, PSp);

    dim3 gAV(L_ / 128, B_ * H_);       // (16, 32)
    av_fused<<<gAV, 256, AV_SMEM>>>(attn, PSp);

    out_proj<<<dim3(D_ / 128, BL_ / 128), 256, PJ_SMEM>>>(Ch, Cl, Wth + 3 * WSZ, Wtl + 3 * WSZ,
                                                          bo, outp);
}